// round 4
// baseline (speedup 1.0000x reference)
#include <cuda_runtime.h>
#include <math.h>

#define CB   2
#define CS   2048
#define CD   1024
#define CH   8
#define CDK  128
#define CVD  2048
#define CDV  256
#define CFFN 4096
#define CBS  (CB*CS)   // 4096 rows

// ---------------- scratch (device globals; no allocation allowed) -------------
__device__ float g_Xn [CBS*CD];
__device__ float g_Q  [CBS*CD];
__device__ float g_K  [CBS*CD];
__device__ float g_V  [CBS*CVD];
__device__ float g_G  [CBS*CVD];
__device__ float g_Y  [CBS*CVD];
__device__ float g_X2 [CBS*CD];
__device__ float g_H1 [CBS*CFFN];
__device__ float g_WqP[CD*CD];
__device__ float g_WkP[CD*CD];
__device__ float g_WvP[CD*CVD];

// ---------------- helpers ----------------------------------------------------
__device__ __forceinline__ float warpsum(float v) {
    #pragma unroll
    for (int o = 16; o; o >>= 1) v += __shfl_xor_sync(0xffffffffu, v, o);
    return v;
}
__device__ __forceinline__ float gelu_f(float x) {
    return 0.5f * x * (1.0f + erff(x * 0.70710678118654752f));
}

// ---------------- layernorm over D=1024, one block per row -------------------
__global__ void ln_kernel(const float* __restrict__ x, const float* __restrict__ w,
                          const float* __restrict__ bb, float* __restrict__ y)
{
    __shared__ float s_sum[8], s_sq[8];
    __shared__ float s_mu, s_rstd;
    const int row = blockIdx.x;
    const int tid = threadIdx.x;
    const float4 v = ((const float4*)(x + (size_t)row * CD))[tid];
    float s = v.x + v.y + v.z + v.w;
    float q = v.x*v.x + v.y*v.y + v.z*v.z + v.w*v.w;
    s = warpsum(s); q = warpsum(q);
    if ((tid & 31) == 0) { s_sum[tid >> 5] = s; s_sq[tid >> 5] = q; }
    __syncthreads();
    if (tid == 0) {
        float ts = 0.f, tq = 0.f;
        #pragma unroll
        for (int i = 0; i < 8; i++) { ts += s_sum[i]; tq += s_sq[i]; }
        float mu  = ts * (1.f / CD);
        float var = tq * (1.f / CD) - mu * mu;
        s_mu = mu; s_rstd = rsqrtf(var + 1e-5f);
    }
    __syncthreads();
    const float mu = s_mu, r = s_rstd;
    const float4 wv = ((const float4*)w)[tid];
    const float4 bv = ((const float4*)bb)[tid];
    float4 o;
    o.x = (v.x - mu) * r * wv.x + bv.x;
    o.y = (v.y - mu) * r * wv.y + bv.y;
    o.z = (v.z - mu) * r * wv.z + bv.z;
    o.w = (v.w - mu) * r * wv.w + bv.w;
    ((float4*)(y + (size_t)row * CD))[tid] = o;
}

// ---------------- weight repack [H][D][dkv] -> [D][H*dkv] ---------------------
__global__ void pack_w_kernel(const float* __restrict__ src, float* __restrict__ dst, int DKV)
{
    const int idx = blockIdx.x * 256 + threadIdx.x;
    const int k = idx % DKV;
    const int d = (idx / DKV) & (CD - 1);
    const int h = idx / (DKV * CD);
    dst[(size_t)d * (CH * DKV) + h * DKV + k] = src[idx];
}

// ---------------- SGEMM: C[M,N] = A[M,K]*B[K,N], 128x128x8, double-buffered ---
// EPI: 0 none, 1 +res, 2 +bias->gelu, 3 +bias+res
template<int EPI>
__global__ __launch_bounds__(256)
void sgemm_kernel(const float* __restrict__ A, const float* __restrict__ B,
                  float* __restrict__ C, int M, int N, int K,
                  const float* __restrict__ bias, const float* __restrict__ res)
{
    __shared__ float As[2][8][128];
    __shared__ float Bs[2][8][128];
    const int bm = blockIdx.y * 128;
    const int bn = blockIdx.x * 128;
    const int tid = threadIdx.x;

    const int aRow = tid >> 1;
    const int aK   = (tid & 1) << 2;
    const int bRow = tid >> 5;
    const int bCol = (tid & 31) << 2;
    const float* Ap = A + (size_t)(bm + aRow) * K + aK;
    const float* Bp = B + (size_t)bRow * N + bn + bCol;

    const int ty = tid >> 4;   // rows ty*8
    const int tx = tid & 15;   // cols tx*8

    float acc[8][8];
    #pragma unroll
    for (int i = 0; i < 8; i++)
        #pragma unroll
        for (int j = 0; j < 8; j++) acc[i][j] = 0.f;

    float4 a  = *(const float4*)Ap;
    float4 b4 = *(const float4*)Bp;
    As[0][aK+0][aRow] = a.x; As[0][aK+1][aRow] = a.y;
    As[0][aK+2][aRow] = a.z; As[0][aK+3][aRow] = a.w;
    *(float4*)&Bs[0][bRow][bCol] = b4;
    __syncthreads();

    int buf = 0;
    for (int k0 = 8; k0 <= K; k0 += 8) {
        if (k0 < K) {
            a  = *(const float4*)(Ap + k0);
            b4 = *(const float4*)(Bp + (size_t)k0 * N);
        }
        #pragma unroll
        for (int kk = 0; kk < 8; kk++) {
            float ar[8], br[8];
            *(float4*)(ar)   = *(const float4*)&As[buf][kk][ty*8];
            *(float4*)(ar+4) = *(const float4*)&As[buf][kk][ty*8+4];
            *(float4*)(br)   = *(const float4*)&Bs[buf][kk][tx*8];
            *(float4*)(br+4) = *(const float4*)&Bs[buf][kk][tx*8+4];
            #pragma unroll
            for (int i = 0; i < 8; i++)
                #pragma unroll
                for (int j = 0; j < 8; j++)
                    acc[i][j] = fmaf(ar[i], br[j], acc[i][j]);
        }
        if (k0 < K) {
            buf ^= 1;
            As[buf][aK+0][aRow] = a.x; As[buf][aK+1][aRow] = a.y;
            As[buf][aK+2][aRow] = a.z; As[buf][aK+3][aRow] = a.w;
            *(float4*)&Bs[buf][bRow][bCol] = b4;
            __syncthreads();
        }
    }

    #pragma unroll
    for (int i = 0; i < 8; i++) {
        const int row = bm + ty*8 + i;
        float* Cp = C + (size_t)row * N + bn + tx*8;
        #pragma unroll
        for (int jj = 0; jj < 8; jj += 4) {
            float4 v = make_float4(acc[i][jj], acc[i][jj+1], acc[i][jj+2], acc[i][jj+3]);
            if (EPI == 2 || EPI == 3) {
                const float4 bv = *(const float4*)(bias + bn + tx*8 + jj);
                v.x += bv.x; v.y += bv.y; v.z += bv.z; v.w += bv.w;
            }
            if (EPI == 2) {
                v.x = gelu_f(v.x); v.y = gelu_f(v.y);
                v.z = gelu_f(v.z); v.w = gelu_f(v.w);
            }
            if (EPI == 1 || EPI == 3) {
                const float4 rv = *(const float4*)(res + (size_t)row * N + bn + tx*8 + jj);
                v.x += rv.x; v.y += rv.y; v.z += rv.z; v.w += rv.w;
            }
            *(float4*)(Cp + jj) = v;
        }
    }
}

// ---------------- xPos rotary (Q in place, K in place w/ inverse scale) -------
__global__ void xpos_kernel(float* __restrict__ Q, float* __restrict__ K)
{
    const int idx = blockIdx.x * 256 + threadIdx.x;   // B*S*H*64 threads
    const int j = idx & 63;
    const int h = (idx >> 6) & 7;
    const int s = (idx >> 9) & 2047;
    const int b = idx >> 20;

    const double invf  = exp2(-(double)j * (13.287712379549449 / 64.0)); // 10000^(-j/64)
    const double theta = (double)s * invf;
    const double sv    = (2.0 * j + 0.4 * 128.0) / (1.4 * 128.0);
    const double e     = log2(sv) * ((double)s / 512.0);
    const float scq = (float)exp2(e);
    const float sck = (float)exp2(-e);
    double snd, csd;
    sincos(theta, &snd, &csd);
    const float sn = (float)snd, cs = (float)csd;

    const size_t base = ((size_t)(b * CS + s)) * CD + h * CDK + 2 * j;
    const float q0 = Q[base], q1 = Q[base + 1];
    Q[base]     = (q0 * cs - q1 * sn) * scq;
    Q[base + 1] = (q1 * cs + q0 * sn) * scq;
    const float k0 = K[base], k1 = K[base + 1];
    K[base]     = (k0 * cs - k1 * sn) * sck;
    K[base + 1] = (k1 * cs + k0 * sn) * sck;
}

// ---------------- fused retention: Y = (QK^T ∘ decay, causal) V ---------------
// grid (S/64, H, B); 256 threads; dynamic smem
__global__ __launch_bounds__(256)
void retention_kernel(const float* __restrict__ Q, const float* __restrict__ K,
                      const float* __restrict__ V, float* __restrict__ Y)
{
    extern __shared__ float sm[];
    float* Qs   = sm;                 // 64 x 132
    float* Ks   = Qs  + 64 * 132;     // 64 x 132
    float* Vs   = Ks  + 64 * 132;     // 64 x 260
    float* SsT  = Vs  + 64 * 260;     // 64 x 68   [t][s]
    float* rowf = SsT + 64 * 68;      // 64
    float* colf = rowf + 64;          // 64

    const int sb = blockIdx.x, h = blockIdx.y, b = blockIdx.z;
    const int qs = sb * 64;
    const int tid = threadIdx.x;
    const int tx = tid & 31;
    const int ty = tid >> 5;

    const double lg = log(1.0/32.0) + (double)h * ((log(1.0/512.0) - log(1.0/32.0)) / 7.0);
    const float l2g = (float)log2(1.0 - exp(lg));   // log2(gamma_h)

    const float* Qbase = Q + ((size_t)(b * CS + qs)) * CD + h * CDK;
    for (int i = tid; i < 64 * 32; i += 256) {
        int r = i >> 5, c4 = (i & 31) << 2;
        *(float4*)(Qs + r * 132 + c4) = *(const float4*)(Qbase + (size_t)r * CD + c4);
    }
    if (tid < 64) rowf[tid] = exp2f((float)tid * l2g);     // gamma^{s'}

    float acc[8][8];
    #pragma unroll
    for (int i = 0; i < 8; i++)
        #pragma unroll
        for (int j = 0; j < 8; j++) acc[i][j] = 0.f;

    for (int ts = 0; ts <= qs; ts += 64) {
        __syncthreads();
        const float* Kbase = K + ((size_t)(b * CS + ts)) * CD + h * CDK;
        for (int i = tid; i < 64 * 32; i += 256) {
            int r = i >> 5, c4 = (i & 31) << 2;
            *(float4*)(Ks + r * 132 + c4) = *(const float4*)(Kbase + (size_t)r * CD + c4);
        }
        const float* Vbase = V + ((size_t)(b * CS + ts)) * CVD + h * CDV;
        for (int i = tid; i < 64 * 64; i += 256) {
            int r = i >> 6, c4 = (i & 63) << 2;
            *(float4*)(Vs + r * 260 + c4) = *(const float4*)(Vbase + (size_t)r * CVD + c4);
        }
        if (tid < 64) colf[tid] = exp2f((float)(qs - ts - tid) * l2g);  // gamma^{qs-t}
        __syncthreads();

        // scores: rows ty*8+i, cols tx + 32*j
        float sc[8][2];
        #pragma unroll
        for (int i = 0; i < 8; i++) { sc[i][0] = 0.f; sc[i][1] = 0.f; }

        for (int k4 = 0; k4 < 128; k4 += 4) {
            const float4 kv0 = *(const float4*)(Ks + tx * 132 + k4);
            const float4 kv1 = *(const float4*)(Ks + (tx + 32) * 132 + k4);
            #pragma unroll
            for (int i = 0; i < 8; i++) {
                const float4 qv = *(const float4*)(Qs + (ty * 8 + i) * 132 + k4);
                sc[i][0] += qv.x*kv0.x + qv.y*kv0.y + qv.z*kv0.z + qv.w*kv0.w;
                sc[i][1] += qv.x*kv1.x + qv.y*kv1.y + qv.z*kv1.z + qv.w*kv1.w;
            }
        }
        const bool diag = (ts == qs);
        #pragma unroll
        for (int j = 0; j < 2; j++) {
            const int tp = tx + 32 * j;
            const float cf = colf[tp];
            #pragma unroll
            for (int i = 0; i < 8; i++) {
                const int sp = ty * 8 + i;
                float d = rowf[sp] * cf;            // gamma^{s-t}
                if (diag && sp < tp) d = 0.f;       // causal mask
                SsT[tp * 68 + sp] = sc[i][j] * d;
            }
        }
        __syncthreads();

        // AV: rows ty*8+i, cols {tx*4..+3} and {128+tx*4..+3}
        #pragma unroll 4
        for (int t = 0; t < 64; t++) {
            float s8[8];
            *(float4*)(s8)     = *(const float4*)(SsT + t * 68 + ty * 8);
            *(float4*)(s8 + 4) = *(const float4*)(SsT + t * 68 + ty * 8 + 4);
            const float4 va = *(const float4*)(Vs + t * 260 + tx * 4);
            const float4 vb = *(const float4*)(Vs + t * 260 + 128 + tx * 4);
            #pragma unroll
            for (int i = 0; i < 8; i++) {
                acc[i][0] = fmaf(s8[i], va.x, acc[i][0]);
                acc[i][1] = fmaf(s8[i], va.y, acc[i][1]);
                acc[i][2] = fmaf(s8[i], va.z, acc[i][2]);
                acc[i][3] = fmaf(s8[i], va.w, acc[i][3]);
                acc[i][4] = fmaf(s8[i], vb.x, acc[i][4]);
                acc[i][5] = fmaf(s8[i], vb.y, acc[i][5]);
                acc[i][6] = fmaf(s8[i], vb.z, acc[i][6]);
                acc[i][7] = fmaf(s8[i], vb.w, acc[i][7]);
            }
        }
    }

    float* Ybase = Y + ((size_t)(b * CS + qs)) * CVD + h * CDV;
    #pragma unroll
    for (int i = 0; i < 8; i++) {
        const int r = ty * 8 + i;
        *(float4*)(Ybase + (size_t)r * CVD + tx * 4)
            = make_float4(acc[i][0], acc[i][1], acc[i][2], acc[i][3]);
        *(float4*)(Ybase + (size_t)r * CVD + 128 + tx * 4)
            = make_float4(acc[i][4], acc[i][5], acc[i][6], acc[i][7]);
    }
}

// ---------------- groupnorm over DV=256 per (b,s,h) + SiLU gate ---------------
__global__ void gnorm_gate_kernel(const float* __restrict__ Yin, const float* __restrict__ G,
                                  const float* __restrict__ gw, const float* __restrict__ gb,
                                  float* __restrict__ out)
{
    const int warp = threadIdx.x >> 5, lane = threadIdx.x & 31;
    const int g = blockIdx.x * 8 + warp;     // group = (b*S+s)*H + h
    const int h = g & 7;
    const float4* yb = (const float4*)(Yin + (size_t)g * 256);
    const float4 v0 = yb[lane], v1 = yb[lane + 32];
    float s = v0.x+v0.y+v0.z+v0.w + v1.x+v1.y+v1.z+v1.w;
    float q = v0.x*v0.x+v0.y*v0.y+v0.z*v0.z+v0.w*v0.w
            + v1.x*v1.x+v1.y*v1.y+v1.z*v1.z+v1.w*v1.w;
    s = warpsum(s); q = warpsum(q);
    const float mu  = s * (1.f / 256.f);
    const float var = q * (1.f / 256.f) - mu * mu;
    const float r   = rsqrtf(var + 1e-5f);

    const float4* gB = (const float4*)(G + (size_t)g * 256);
    const float4 g0 = gB[lane], g1 = gB[lane + 32];
    const int c0 = h * 256 + lane * 4, c1 = c0 + 128;
    const float4 w0 = *(const float4*)(gw + c0), w1 = *(const float4*)(gw + c1);
    const float4 b0 = *(const float4*)(gb + c0), b1 = *(const float4*)(gb + c1);

    float4 o0, o1;
    o0.x = ((v0.x-mu)*r*w0.x + b0.x) * (g0.x / (1.f + expf(-g0.x)));
    o0.y = ((v0.y-mu)*r*w0.y + b0.y) * (g0.y / (1.f + expf(-g0.y)));
    o0.z = ((v0.z-mu)*r*w0.z + b0.z) * (g0.z / (1.f + expf(-g0.z)));
    o0.w = ((v0.w-mu)*r*w0.w + b0.w) * (g0.w / (1.f + expf(-g0.w)));
    o1.x = ((v1.x-mu)*r*w1.x + b1.x) * (g1.x / (1.f + expf(-g1.x)));
    o1.y = ((v1.y-mu)*r*w1.y + b1.y) * (g1.y / (1.f + expf(-g1.y)));
    o1.z = ((v1.z-mu)*r*w1.z + b1.z) * (g1.z / (1.f + expf(-g1.z)));
    o1.w = ((v1.w-mu)*r*w1.w + b1.w) * (g1.w / (1.f + expf(-g1.w)));

    float4* ob = (float4*)(out + (size_t)g * 256);
    ob[lane] = o0; ob[lane + 32] = o1;
}

// ---------------- launch ------------------------------------------------------
extern "C" void kernel_launch(void* const* d_in, const int* in_sizes, int n_in,
                              void* d_out, int out_size)
{
    const float* X     = (const float*)d_in[0];
    const float* Wq    = (const float*)d_in[1];
    const float* Wk    = (const float*)d_in[2];
    const float* Wv    = (const float*)d_in[3];
    const float* W_G   = (const float*)d_in[4];
    const float* W_O   = (const float*)d_in[5];
    const float* gn_w  = (const float*)d_in[6];
    const float* gn_b  = (const float*)d_in[7];
    const float* ln1_w = (const float*)d_in[8];
    const float* ln1_b = (const float*)d_in[9];
    const float* ln2_w = (const float*)d_in[10];
    const float* ln2_b = (const float*)d_in[11];
    const float* fw1   = (const float*)d_in[12];
    const float* fb1   = (const float*)d_in[13];
    const float* fw2   = (const float*)d_in[14];
    const float* fb2   = (const float*)d_in[15];

    float *Xn, *Qb, *Kb, *Vb, *Gb, *Yb, *X2, *H1, *WqP, *WkP, *WvP;
    cudaGetSymbolAddress((void**)&Xn,  g_Xn);
    cudaGetSymbolAddress((void**)&Qb,  g_Q);
    cudaGetSymbolAddress((void**)&Kb,  g_K);
    cudaGetSymbolAddress((void**)&Vb,  g_V);
    cudaGetSymbolAddress((void**)&Gb,  g_G);
    cudaGetSymbolAddress((void**)&Yb,  g_Y);
    cudaGetSymbolAddress((void**)&X2,  g_X2);
    cudaGetSymbolAddress((void**)&H1,  g_H1);
    cudaGetSymbolAddress((void**)&WqP, g_WqP);
    cudaGetSymbolAddress((void**)&WkP, g_WkP);
    cudaGetSymbolAddress((void**)&WvP, g_WvP);

    const int RET_SMEM = (64*132 + 64*132 + 64*260 + 64*68 + 128) * 4; // 152064 B
    cudaFuncSetAttribute(retention_kernel,
                         cudaFuncAttributeMaxDynamicSharedMemorySize, RET_SMEM);

    // LN1
    ln_kernel<<<CBS, 256>>>(X, ln1_w, ln1_b, Xn);

    // repack weights
    pack_w_kernel<<<(CH*CD*CDK)/256, 256>>>(Wq, WqP, CDK);
    pack_w_kernel<<<(CH*CD*CDK)/256, 256>>>(Wk, WkP, CDK);
    pack_w_kernel<<<(CH*CD*CDV)/256, 256>>>(Wv, WvP, CDV);

    // projections
    sgemm_kernel<0><<<dim3(CD/128,  CBS/128), 256>>>(Xn, WqP, Qb, CBS, CD,  CD, nullptr, nullptr);
    sgemm_kernel<0><<<dim3(CD/128,  CBS/128), 256>>>(Xn, WkP, Kb, CBS, CD,  CD, nullptr, nullptr);
    sgemm_kernel<0><<<dim3(CVD/128, CBS/128), 256>>>(Xn, WvP, Vb, CBS, CVD, CD, nullptr, nullptr);
    sgemm_kernel<0><<<dim3(CVD/128, CBS/128), 256>>>(Xn, W_G, Gb, CBS, CVD, CD, nullptr, nullptr);

    // xPos
    xpos_kernel<<<(CB*CS*CH*64)/256, 256>>>(Qb, Kb);

    // retention
    retention_kernel<<<dim3(CS/64, CH, CB), 256, RET_SMEM>>>(Qb, Kb, Vb, Yb);

    // groupnorm + silu gate (in place into Yb)
    gnorm_gate_kernel<<<(CBS*CH)/8, 256>>>(Yb, Gb, gn_w, gn_b, Yb);

    // output projection + residual X -> X2
    sgemm_kernel<1><<<dim3(CD/128, CBS/128), 256>>>(Yb, W_O, X2, CBS, CD, CVD, nullptr, X);

    // LN2
    ln_kernel<<<CBS, 256>>>(X2, ln2_w, ln2_b, Xn);

    // FFN
    sgemm_kernel<2><<<dim3(CFFN/128, CBS/128), 256>>>(Xn, fw1, H1, CBS, CFFN, CD, fb1, nullptr);
    sgemm_kernel<3><<<dim3(CD/128,  CBS/128), 256>>>(H1, fw2, (float*)d_out, CBS, CD, CFFN, fb2, X2);
}

// round 5
// speedup vs baseline: 1.0014x; 1.0014x over previous
#include <cuda_runtime.h>
#include <math.h>

#define CB   2
#define CS   2048
#define CD   1024
#define CH   8
#define CDK  128
#define CVD  2048
#define CDV  256
#define CFFN 4096
#define CBS  (CB*CS)   // 4096 rows

// ---------------- scratch (device globals; no allocation allowed) -------------
__device__ float g_Xn [CBS*CD];
__device__ float g_Q  [CBS*CD];
__device__ float g_K  [CBS*CD];
__device__ float g_V  [CBS*CVD];
__device__ float g_G  [CBS*CVD];
__device__ float g_Y  [CBS*CVD];
__device__ float g_X2 [CBS*CD];
__device__ float g_H1 [CBS*CFFN];
__device__ float g_WqP[CD*CD];
__device__ float g_WkP[CD*CD];
__device__ float g_WvP[CD*CVD];

// ---------------- helpers ----------------------------------------------------
__device__ __forceinline__ float warpsum(float v) {
    #pragma unroll
    for (int o = 16; o; o >>= 1) v += __shfl_xor_sync(0xffffffffu, v, o);
    return v;
}
__device__ __forceinline__ float gelu_f(float x) {
    return 0.5f * x * (1.0f + erff(x * 0.70710678118654752f));
}

// ---------------- layernorm over D=1024, one block per row -------------------
__global__ void ln_kernel(const float* __restrict__ x, const float* __restrict__ w,
                          const float* __restrict__ bb, float* __restrict__ y)
{
    __shared__ float s_sum[8], s_sq[8];
    __shared__ float s_mu, s_rstd;
    const int row = blockIdx.x;
    const int tid = threadIdx.x;
    const float4 v = ((const float4*)(x + (size_t)row * CD))[tid];
    float s = v.x + v.y + v.z + v.w;
    float q = v.x*v.x + v.y*v.y + v.z*v.z + v.w*v.w;
    s = warpsum(s); q = warpsum(q);
    if ((tid & 31) == 0) { s_sum[tid >> 5] = s; s_sq[tid >> 5] = q; }
    __syncthreads();
    if (tid == 0) {
        float ts = 0.f, tq = 0.f;
        #pragma unroll
        for (int i = 0; i < 8; i++) { ts += s_sum[i]; tq += s_sq[i]; }
        float mu  = ts * (1.f / CD);
        float var = tq * (1.f / CD) - mu * mu;
        s_mu = mu; s_rstd = rsqrtf(var + 1e-5f);
    }
    __syncthreads();
    const float mu = s_mu, r = s_rstd;
    const float4 wv = ((const float4*)w)[tid];
    const float4 bv = ((const float4*)bb)[tid];
    float4 o;
    o.x = (v.x - mu) * r * wv.x + bv.x;
    o.y = (v.y - mu) * r * wv.y + bv.y;
    o.z = (v.z - mu) * r * wv.z + bv.z;
    o.w = (v.w - mu) * r * wv.w + bv.w;
    ((float4*)(y + (size_t)row * CD))[tid] = o;
}

// ---------------- weight repack [H][D][dkv] -> [D][H*dkv] ---------------------
__global__ void pack_w_kernel(const float* __restrict__ src, float* __restrict__ dst, int DKV)
{
    const int idx = blockIdx.x * 256 + threadIdx.x;
    const int k = idx % DKV;
    const int d = (idx / DKV) & (CD - 1);
    const int h = idx / (DKV * CD);
    dst[(size_t)d * (CH * DKV) + h * DKV + k] = src[idx];
}

// ---------------- SGEMM: C[M,N] = A[M,K]*B[K,N], 128x128x8, double-buffered ---
// EPI: 0 none, 1 +res, 2 +bias->gelu, 3 +bias+res
template<int EPI>
__global__ __launch_bounds__(256)
void sgemm_kernel(const float* __restrict__ A, const float* __restrict__ B,
                  float* __restrict__ C, int M, int N, int K,
                  const float* __restrict__ bias, const float* __restrict__ res)
{
    __shared__ float As[2][8][128];
    __shared__ float Bs[2][8][128];
    const int bm = blockIdx.y * 128;
    const int bn = blockIdx.x * 128;
    const int tid = threadIdx.x;

    const int aRow = tid >> 1;
    const int aK   = (tid & 1) << 2;
    const int bRow = tid >> 5;
    const int bCol = (tid & 31) << 2;
    const float* Ap = A + (size_t)(bm + aRow) * K + aK;
    const float* Bp = B + (size_t)bRow * N + bn + bCol;

    const int ty = tid >> 4;   // rows ty*8
    const int tx = tid & 15;   // cols tx*8

    float acc[8][8];
    #pragma unroll
    for (int i = 0; i < 8; i++)
        #pragma unroll
        for (int j = 0; j < 8; j++) acc[i][j] = 0.f;

    float4 a  = *(const float4*)Ap;
    float4 b4 = *(const float4*)Bp;
    As[0][aK+0][aRow] = a.x; As[0][aK+1][aRow] = a.y;
    As[0][aK+2][aRow] = a.z; As[0][aK+3][aRow] = a.w;
    *(float4*)&Bs[0][bRow][bCol] = b4;
    __syncthreads();

    int buf = 0;
    for (int k0 = 8; k0 <= K; k0 += 8) {
        if (k0 < K) {
            a  = *(const float4*)(Ap + k0);
            b4 = *(const float4*)(Bp + (size_t)k0 * N);
        }
        #pragma unroll
        for (int kk = 0; kk < 8; kk++) {
            float ar[8], br[8];
            *(float4*)(ar)   = *(const float4*)&As[buf][kk][ty*8];
            *(float4*)(ar+4) = *(const float4*)&As[buf][kk][ty*8+4];
            *(float4*)(br)   = *(const float4*)&Bs[buf][kk][tx*8];
            *(float4*)(br+4) = *(const float4*)&Bs[buf][kk][tx*8+4];
            #pragma unroll
            for (int i = 0; i < 8; i++)
                #pragma unroll
                for (int j = 0; j < 8; j++)
                    acc[i][j] = fmaf(ar[i], br[j], acc[i][j]);
        }
        if (k0 < K) {
            buf ^= 1;
            As[buf][aK+0][aRow] = a.x; As[buf][aK+1][aRow] = a.y;
            As[buf][aK+2][aRow] = a.z; As[buf][aK+3][aRow] = a.w;
            *(float4*)&Bs[buf][bRow][bCol] = b4;
            __syncthreads();
        }
    }

    #pragma unroll
    for (int i = 0; i < 8; i++) {
        const int row = bm + ty*8 + i;
        float* Cp = C + (size_t)row * N + bn + tx*8;
        #pragma unroll
        for (int jj = 0; jj < 8; jj += 4) {
            float4 v = make_float4(acc[i][jj], acc[i][jj+1], acc[i][jj+2], acc[i][jj+3]);
            if (EPI == 2 || EPI == 3) {
                const float4 bv = *(const float4*)(bias + bn + tx*8 + jj);
                v.x += bv.x; v.y += bv.y; v.z += bv.z; v.w += bv.w;
            }
            if (EPI == 2) {
                v.x = gelu_f(v.x); v.y = gelu_f(v.y);
                v.z = gelu_f(v.z); v.w = gelu_f(v.w);
            }
            if (EPI == 1 || EPI == 3) {
                const float4 rv = *(const float4*)(res + (size_t)row * N + bn + tx*8 + jj);
                v.x += rv.x; v.y += rv.y; v.z += rv.z; v.w += rv.w;
            }
            *(float4*)(Cp + jj) = v;
        }
    }
}

// ---------------- xPos rotary (Q in place, K in place w/ inverse scale) -------
__global__ void xpos_kernel(float* __restrict__ Q, float* __restrict__ K)
{
    const int idx = blockIdx.x * 256 + threadIdx.x;   // B*S*H*64 threads
    const int j = idx & 63;
    const int h = (idx >> 6) & 7;
    const int s = (idx >> 9) & 2047;
    const int b = idx >> 20;

    const double invf  = exp2(-(double)j * (13.287712379549449 / 64.0)); // 10000^(-j/64)
    const double theta = (double)s * invf;
    const double sv    = (2.0 * j + 0.4 * 128.0) / (1.4 * 128.0);
    const double e     = log2(sv) * ((double)s / 512.0);
    const float scq = (float)exp2(e);
    const float sck = (float)exp2(-e);
    double snd, csd;
    sincos(theta, &snd, &csd);
    const float sn = (float)snd, cs = (float)csd;

    const size_t base = ((size_t)(b * CS + s)) * CD + h * CDK + 2 * j;
    const float q0 = Q[base], q1 = Q[base + 1];
    Q[base]     = (q0 * cs - q1 * sn) * scq;
    Q[base + 1] = (q1 * cs + q0 * sn) * scq;
    const float k0 = K[base], k1 = K[base + 1];
    K[base]     = (k0 * cs - k1 * sn) * sck;
    K[base + 1] = (k1 * cs + k0 * sn) * sck;
}

// ---------------- fused retention: Y = (QK^T ∘ decay, causal) V ---------------
// grid (S/64, H, B); 256 threads; dynamic smem
__global__ __launch_bounds__(256)
void retention_kernel(const float* __restrict__ Q, const float* __restrict__ K,
                      const float* __restrict__ V, float* __restrict__ Y)
{
    extern __shared__ float sm[];
    float* Qs   = sm;                 // 64 x 132
    float* Ks   = Qs  + 64 * 132;     // 64 x 132
    float* Vs   = Ks  + 64 * 132;     // 64 x 260
    float* SsT  = Vs  + 64 * 260;     // 64 x 68   [t][s]
    float* rowf = SsT + 64 * 68;      // 64
    float* colf = rowf + 64;          // 64

    const int sb = blockIdx.x, h = blockIdx.y, b = blockIdx.z;
    const int qs = sb * 64;
    const int tid = threadIdx.x;
    const int tx = tid & 31;
    const int ty = tid >> 5;

    const double lg = log(1.0/32.0) + (double)h * ((log(1.0/512.0) - log(1.0/32.0)) / 7.0);
    const float l2g = (float)log2(1.0 - exp(lg));   // log2(gamma_h)

    const float* Qbase = Q + ((size_t)(b * CS + qs)) * CD + h * CDK;
    for (int i = tid; i < 64 * 32; i += 256) {
        int r = i >> 5, c4 = (i & 31) << 2;
        *(float4*)(Qs + r * 132 + c4) = *(const float4*)(Qbase + (size_t)r * CD + c4);
    }
    if (tid < 64) rowf[tid] = exp2f((float)tid * l2g);     // gamma^{s'}

    float acc[8][8];
    #pragma unroll
    for (int i = 0; i < 8; i++)
        #pragma unroll
        for (int j = 0; j < 8; j++) acc[i][j] = 0.f;

    for (int ts = 0; ts <= qs; ts += 64) {
        __syncthreads();
        const float* Kbase = K + ((size_t)(b * CS + ts)) * CD + h * CDK;
        for (int i = tid; i < 64 * 32; i += 256) {
            int r = i >> 5, c4 = (i & 31) << 2;
            *(float4*)(Ks + r * 132 + c4) = *(const float4*)(Kbase + (size_t)r * CD + c4);
        }
        const float* Vbase = V + ((size_t)(b * CS + ts)) * CVD + h * CDV;
        for (int i = tid; i < 64 * 64; i += 256) {
            int r = i >> 6, c4 = (i & 63) << 2;
            *(float4*)(Vs + r * 260 + c4) = *(const float4*)(Vbase + (size_t)r * CVD + c4);
        }
        if (tid < 64) colf[tid] = exp2f((float)(qs - ts - tid) * l2g);  // gamma^{qs-t}
        __syncthreads();

        // scores: rows ty*8+i, cols tx + 32*j
        float sc[8][2];
        #pragma unroll
        for (int i = 0; i < 8; i++) { sc[i][0] = 0.f; sc[i][1] = 0.f; }

        for (int k4 = 0; k4 < 128; k4 += 4) {
            const float4 kv0 = *(const float4*)(Ks + tx * 132 + k4);
            const float4 kv1 = *(const float4*)(Ks + (tx + 32) * 132 + k4);
            #pragma unroll
            for (int i = 0; i < 8; i++) {
                const float4 qv = *(const float4*)(Qs + (ty * 8 + i) * 132 + k4);
                sc[i][0] += qv.x*kv0.x + qv.y*kv0.y + qv.z*kv0.z + qv.w*kv0.w;
                sc[i][1] += qv.x*kv1.x + qv.y*kv1.y + qv.z*kv1.z + qv.w*kv1.w;
            }
        }
        const bool diag = (ts == qs);
        #pragma unroll
        for (int j = 0; j < 2; j++) {
            const int tp = tx + 32 * j;
            const float cf = colf[tp];
            #pragma unroll
            for (int i = 0; i < 8; i++) {
                const int sp = ty * 8 + i;
                float d = rowf[sp] * cf;            // gamma^{s-t}
                if (diag && sp < tp) d = 0.f;       // causal mask
                SsT[tp * 68 + sp] = sc[i][j] * d;
            }
        }
        __syncthreads();

        // AV: rows ty*8+i, cols {tx*4..+3} and {128+tx*4..+3}
        #pragma unroll 4
        for (int t = 0; t < 64; t++) {
            float s8[8];
            *(float4*)(s8)     = *(const float4*)(SsT + t * 68 + ty * 8);
            *(float4*)(s8 + 4) = *(const float4*)(SsT + t * 68 + ty * 8 + 4);
            const float4 va = *(const float4*)(Vs + t * 260 + tx * 4);
            const float4 vb = *(const float4*)(Vs + t * 260 + 128 + tx * 4);
            #pragma unroll
            for (int i = 0; i < 8; i++) {
                acc[i][0] = fmaf(s8[i], va.x, acc[i][0]);
                acc[i][1] = fmaf(s8[i], va.y, acc[i][1]);
                acc[i][2] = fmaf(s8[i], va.z, acc[i][2]);
                acc[i][3] = fmaf(s8[i], va.w, acc[i][3]);
                acc[i][4] = fmaf(s8[i], vb.x, acc[i][4]);
                acc[i][5] = fmaf(s8[i], vb.y, acc[i][5]);
                acc[i][6] = fmaf(s8[i], vb.z, acc[i][6]);
                acc[i][7] = fmaf(s8[i], vb.w, acc[i][7]);
            }
        }
    }

    float* Ybase = Y + ((size_t)(b * CS + qs)) * CVD + h * CDV;
    #pragma unroll
    for (int i = 0; i < 8; i++) {
        const int r = ty * 8 + i;
        *(float4*)(Ybase + (size_t)r * CVD + tx * 4)
            = make_float4(acc[i][0], acc[i][1], acc[i][2], acc[i][3]);
        *(float4*)(Ybase + (size_t)r * CVD + 128 + tx * 4)
            = make_float4(acc[i][4], acc[i][5], acc[i][6], acc[i][7]);
    }
}

// ---------------- groupnorm over DV=256 per (b,s,h) + SiLU gate ---------------
__global__ void gnorm_gate_kernel(const float* __restrict__ Yin, const float* __restrict__ G,
                                  const float* __restrict__ gw, const float* __restrict__ gb,
                                  float* __restrict__ out)
{
    const int warp = threadIdx.x >> 5, lane = threadIdx.x & 31;
    const int g = blockIdx.x * 8 + warp;     // group = (b*S+s)*H + h
    const int h = g & 7;
    const float4* yb = (const float4*)(Yin + (size_t)g * 256);
    const float4 v0 = yb[lane], v1 = yb[lane + 32];
    float s = v0.x+v0.y+v0.z+v0.w + v1.x+v1.y+v1.z+v1.w;
    float q = v0.x*v0.x+v0.y*v0.y+v0.z*v0.z+v0.w*v0.w
            + v1.x*v1.x+v1.y*v1.y+v1.z*v1.z+v1.w*v1.w;
    s = warpsum(s); q = warpsum(q);
    const float mu  = s * (1.f / 256.f);
    const float var = q * (1.f / 256.f) - mu * mu;
    const float r   = rsqrtf(var + 1e-5f);

    const float4* gB = (const float4*)(G + (size_t)g * 256);
    const float4 g0 = gB[lane], g1 = gB[lane + 32];
    const int c0 = h * 256 + lane * 4, c1 = c0 + 128;
    const float4 w0 = *(const float4*)(gw + c0), w1 = *(const float4*)(gw + c1);
    const float4 b0 = *(const float4*)(gb + c0), b1 = *(const float4*)(gb + c1);

    float4 o0, o1;
    o0.x = ((v0.x-mu)*r*w0.x + b0.x) * (g0.x / (1.f + expf(-g0.x)));
    o0.y = ((v0.y-mu)*r*w0.y + b0.y) * (g0.y / (1.f + expf(-g0.y)));
    o0.z = ((v0.z-mu)*r*w0.z + b0.z) * (g0.z / (1.f + expf(-g0.z)));
    o0.w = ((v0.w-mu)*r*w0.w + b0.w) * (g0.w / (1.f + expf(-g0.w)));
    o1.x = ((v1.x-mu)*r*w1.x + b1.x) * (g1.x / (1.f + expf(-g1.x)));
    o1.y = ((v1.y-mu)*r*w1.y + b1.y) * (g1.y / (1.f + expf(-g1.y)));
    o1.z = ((v1.z-mu)*r*w1.z + b1.z) * (g1.z / (1.f + expf(-g1.z)));
    o1.w = ((v1.w-mu)*r*w1.w + b1.w) * (g1.w / (1.f + expf(-g1.w)));

    float4* ob = (float4*)(out + (size_t)g * 256);
    ob[lane] = o0; ob[lane + 32] = o1;
}

// ---------------- launch ------------------------------------------------------
extern "C" void kernel_launch(void* const* d_in, const int* in_sizes, int n_in,
                              void* d_out, int out_size)
{
    const float* X     = (const float*)d_in[0];
    const float* Wq    = (const float*)d_in[1];
    const float* Wk    = (const float*)d_in[2];
    const float* Wv    = (const float*)d_in[3];
    const float* W_G   = (const float*)d_in[4];
    const float* W_O   = (const float*)d_in[5];
    const float* gn_w  = (const float*)d_in[6];
    const float* gn_b  = (const float*)d_in[7];
    const float* ln1_w = (const float*)d_in[8];
    const float* ln1_b = (const float*)d_in[9];
    const float* ln2_w = (const float*)d_in[10];
    const float* ln2_b = (const float*)d_in[11];
    const float* fw1   = (const float*)d_in[12];
    const float* fb1   = (const float*)d_in[13];
    const float* fw2   = (const float*)d_in[14];
    const float* fb2   = (const float*)d_in[15];

    float *Xn, *Qb, *Kb, *Vb, *Gb, *Yb, *X2, *H1, *WqP, *WkP, *WvP;
    cudaGetSymbolAddress((void**)&Xn,  g_Xn);
    cudaGetSymbolAddress((void**)&Qb,  g_Q);
    cudaGetSymbolAddress((void**)&Kb,  g_K);
    cudaGetSymbolAddress((void**)&Vb,  g_V);
    cudaGetSymbolAddress((void**)&Gb,  g_G);
    cudaGetSymbolAddress((void**)&Yb,  g_Y);
    cudaGetSymbolAddress((void**)&X2,  g_X2);
    cudaGetSymbolAddress((void**)&H1,  g_H1);
    cudaGetSymbolAddress((void**)&WqP, g_WqP);
    cudaGetSymbolAddress((void**)&WkP, g_WkP);
    cudaGetSymbolAddress((void**)&WvP, g_WvP);

    const int RET_SMEM = (64*132 + 64*132 + 64*260 + 64*68 + 128) * 4; // 152064 B
    cudaFuncSetAttribute(retention_kernel,
                         cudaFuncAttributeMaxDynamicSharedMemorySize, RET_SMEM);

    // LN1
    ln_kernel<<<CBS, 256>>>(X, ln1_w, ln1_b, Xn);

    // repack weights
    pack_w_kernel<<<(CH*CD*CDK)/256, 256>>>(Wq, WqP, CDK);
    pack_w_kernel<<<(CH*CD*CDK)/256, 256>>>(Wk, WkP, CDK);
    pack_w_kernel<<<(CH*CD*CDV)/256, 256>>>(Wv, WvP, CDV);

    // projections
    sgemm_kernel<0><<<dim3(CD/128,  CBS/128), 256>>>(Xn, WqP, Qb, CBS, CD,  CD, nullptr, nullptr);
    sgemm_kernel<0><<<dim3(CD/128,  CBS/128), 256>>>(Xn, WkP, Kb, CBS, CD,  CD, nullptr, nullptr);
    sgemm_kernel<0><<<dim3(CVD/128, CBS/128), 256>>>(Xn, WvP, Vb, CBS, CVD, CD, nullptr, nullptr);
    sgemm_kernel<0><<<dim3(CVD/128, CBS/128), 256>>>(Xn, W_G, Gb, CBS, CVD, CD, nullptr, nullptr);

    // xPos
    xpos_kernel<<<(CB*CS*CH*64)/256, 256>>>(Qb, Kb);

    // retention
    retention_kernel<<<dim3(CS/64, CH, CB), 256, RET_SMEM>>>(Qb, Kb, Vb, Yb);

    // groupnorm + silu gate (in place into Yb)
    gnorm_gate_kernel<<<(CBS*CH)/8, 256>>>(Yb, Gb, gn_w, gn_b, Yb);

    // output projection + residual X -> X2
    sgemm_kernel<1><<<dim3(CD/128, CBS/128), 256>>>(Yb, W_O, X2, CBS, CD, CVD, nullptr, X);

    // LN2
    ln_kernel<<<CBS, 256>>>(X2, ln2_w, ln2_b, Xn);

    // FFN
    sgemm_kernel<2><<<dim3(CFFN/128, CBS/128), 256>>>(Xn, fw1, H1, CBS, CFFN, CD, fb1, nullptr);
    sgemm_kernel<3><<<dim3(CD/128,  CBS/128), 256>>>(H1, fw2, (float*)d_out, CBS, CD, CFFN, fb2, X2);
}

// round 9
// speedup vs baseline: 1.9129x; 1.9102x over previous
#include <cuda_runtime.h>
#include <cuda_bf16.h>
#include <math.h>
#include <stdint.h>

#define CB   2
#define CS   2048
#define CD   1024
#define CH   8
#define CDK  128
#define CVD  2048
#define CDV  256
#define CFFN 4096
#define CBS  (CB*CS)     // 4096 rows
#define CNQ  6144        // fused Q|K|V|G width

// ---------------- scratch (device globals; no allocation allowed) -------------
__device__ float g_QKVG[(size_t)CBS*CNQ];
__device__ float g_Y   [(size_t)CBS*CVD];
__device__ float g_X2  [(size_t)CBS*CD];
__device__ __nv_bfloat16 g_Ah [(size_t)CBS*2048], g_Al [(size_t)CBS*2048];
__device__ __nv_bfloat16 g_H1h[(size_t)CBS*CFFN], g_H1l[(size_t)CBS*CFFN];
__device__ __nv_bfloat16 g_Wqh[(size_t)CNQ*CD],  g_Wql[(size_t)CNQ*CD];
__device__ __nv_bfloat16 g_Woh[(size_t)CD*CVD],  g_Wol[(size_t)CD*CVD];
__device__ __nv_bfloat16 g_F1h[(size_t)CFFN*CD], g_F1l[(size_t)CFFN*CD];
__device__ __nv_bfloat16 g_F2h[(size_t)CD*CFFN], g_F2l[(size_t)CD*CFFN];

// ================= PTX helpers (base sm_103 — no 'a' features) =================
__device__ __forceinline__ uint32_t smem_u32(const void* p) {
    uint32_t a;
    asm("{ .reg .u64 t; cvta.to.shared.u64 t, %1; cvt.u32.u64 %0, t; }" : "=r"(a) : "l"(p));
    return a;
}
#define CP_ASYNC16(dst, src) \
    asm volatile("cp.async.cg.shared.global [%0], [%1], 16;" :: "r"(dst), "l"(src))
#define CP_COMMIT() asm volatile("cp.async.commit_group;" ::: "memory")
#define CP_WAIT(n)  asm volatile("cp.async.wait_group %0;" :: "n"(n) : "memory")

__device__ __forceinline__ void ldsm4(uint32_t* r, uint32_t addr) {
    asm volatile("ldmatrix.sync.aligned.m8n8.x4.shared.b16 {%0,%1,%2,%3}, [%4];"
        : "=r"(r[0]), "=r"(r[1]), "=r"(r[2]), "=r"(r[3]) : "r"(addr));
}
__device__ __forceinline__ void mma_bf16(float* d, const uint32_t* a, const uint32_t* b) {
    asm volatile("mma.sync.aligned.m16n8k16.row.col.f32.bf16.bf16.f32 "
        "{%0,%1,%2,%3}, {%4,%5,%6,%7}, {%8,%9}, {%0,%1,%2,%3};"
        : "+f"(d[0]), "+f"(d[1]), "+f"(d[2]), "+f"(d[3])
        : "r"(a[0]), "r"(a[1]), "r"(a[2]), "r"(a[3]), "r"(b[0]), "r"(b[1]));
}

// ---------------- misc helpers -------------------------------------------------
__device__ __forceinline__ float warpsum(float v) {
    #pragma unroll
    for (int o = 16; o; o >>= 1) v += __shfl_xor_sync(0xffffffffu, v, o);
    return v;
}
__device__ __forceinline__ float gelu_f(float x) {
    return 0.5f * x * (1.0f + erff(x * 0.70710678118654752f));
}
__device__ __forceinline__ void split_bf16(float x, __nv_bfloat16& h, __nv_bfloat16& l) {
    h = __float2bfloat16(x);
    l = __float2bfloat16(x - __bfloat162float(h));
}

// ---------------- layernorm over D=1024 -> split bf16 --------------------------
__global__ void ln_split_kernel(const float* __restrict__ x, const float* __restrict__ w,
                                const float* __restrict__ bb,
                                __nv_bfloat16* __restrict__ yh, __nv_bfloat16* __restrict__ yl)
{
    __shared__ float s_sum[8], s_sq[8];
    __shared__ float s_mu, s_rstd;
    const int row = blockIdx.x;
    const int tid = threadIdx.x;
    const float4 v = ((const float4*)(x + (size_t)row * CD))[tid];
    float s = v.x + v.y + v.z + v.w;
    float q = v.x*v.x + v.y*v.y + v.z*v.z + v.w*v.w;
    s = warpsum(s); q = warpsum(q);
    if ((tid & 31) == 0) { s_sum[tid >> 5] = s; s_sq[tid >> 5] = q; }
    __syncthreads();
    if (tid == 0) {
        float ts = 0.f, tq = 0.f;
        #pragma unroll
        for (int i = 0; i < 8; i++) { ts += s_sum[i]; tq += s_sq[i]; }
        float mu  = ts * (1.f / CD);
        float var = tq * (1.f / CD) - mu * mu;
        s_mu = mu; s_rstd = rsqrtf(var + 1e-5f);
    }
    __syncthreads();
    const float mu = s_mu, r = s_rstd;
    const float4 wv = ((const float4*)w)[tid];
    const float4 bv = ((const float4*)bb)[tid];
    float o0 = (v.x - mu) * r * wv.x + bv.x;
    float o1 = (v.y - mu) * r * wv.y + bv.y;
    float o2 = (v.z - mu) * r * wv.z + bv.z;
    float o3 = (v.w - mu) * r * wv.w + bv.w;
    __nv_bfloat162 hA, hB, lA, lB;
    split_bf16(o0, hA.x, lA.x); split_bf16(o1, hA.y, lA.y);
    split_bf16(o2, hB.x, lB.x); split_bf16(o3, hB.y, lB.y);
    const size_t base = (size_t)row * CD + tid * 4;
    *(__nv_bfloat162*)(yh + base)     = hA;
    *(__nv_bfloat162*)(yh + base + 2) = hB;
    *(__nv_bfloat162*)(yl + base)     = lA;
    *(__nv_bfloat162*)(yl + base + 2) = lB;
}

// ---------------- weight pack: transpose + bf16 split ---------------------------
__global__ void pack_split_kernel(const float* __restrict__ src,
                                  __nv_bfloat16* __restrict__ dh, __nv_bfloat16* __restrict__ dl,
                                  int Dd, int Kk)
{
    __shared__ float t[32][33];
    const int lx = threadIdx.x & 31, ly = threadIdx.x >> 5;
    const int d0 = blockIdx.x * 32;
    const int r0 = blockIdx.y * 32;
    const int h  = r0 / Kk;
    const int k0 = r0 - h * Kk;
    const float* s = src + (size_t)h * Dd * Kk;
    #pragma unroll
    for (int i = ly; i < 32; i += 8)
        t[i][lx] = s[(size_t)(d0 + i) * Kk + k0 + lx];
    __syncthreads();
    #pragma unroll
    for (int i = ly; i < 32; i += 8) {
        float x = t[lx][i];
        __nv_bfloat16 hh, ll;
        split_bf16(x, hh, ll);
        dh[(size_t)(r0 + i) * Dd + d0 + lx] = hh;
        dl[(size_t)(r0 + i) * Dd + d0 + lx] = ll;
    }
}

// ---------------- mma.sync split-bf16 GEMM (128x128 tile, Ktile=64, 2 stages) ---
// smem stage: Ah(16K) Al(16K) Bh(16K) Bl(16K) = 64KB; 2 stages = 128KB
#define MG_STAGE 65536

__device__ __forceinline__ void mg_load_stage(
    uint32_t sbase, int st, int tid,
    const __nv_bfloat16* __restrict__ Ah, const __nv_bfloat16* __restrict__ Al,
    const __nv_bfloat16* __restrict__ Bh, const __nv_bfloat16* __restrict__ Bl,
    int bm, int bn, int K, int kt)
{
    const uint32_t stb = sbase + st * MG_STAGE;
    #pragma unroll
    for (int i = 0; i < 16; i++) {
        int idx  = tid + i * 256;        // 0..4095 chunks of 16B
        int half = idx >> 11;            // 0:A, 1:B
        int m    = (idx >> 10) & 1;      // 0:hi, 1:lo
        int r    = (idx >> 3) & 127;
        int c    = idx & 7;
        const __nv_bfloat16* g = half ? (m ? Bl : Bh) : (m ? Al : Ah);
        const __nv_bfloat16* src = g + (size_t)((half ? bn : bm) + r) * K + kt + c * 8;
        uint32_t dst = stb + (half << 15) + (m << 14) + r * 128 + ((c ^ (r & 7)) << 4);
        CP_ASYNC16(dst, src);
    }
}

// EPI: 0 fp32 store; 1 +res; 2 +bias->gelu->split bf16; 3 +bias+res
template<int EPI>
__global__ __launch_bounds__(256, 1)
void mma_gemm(const __nv_bfloat16* __restrict__ Ah, const __nv_bfloat16* __restrict__ Al,
              const __nv_bfloat16* __restrict__ Bh, const __nv_bfloat16* __restrict__ Bl,
              float* __restrict__ C,
              __nv_bfloat16* __restrict__ Ch, __nv_bfloat16* __restrict__ Cl,
              int N, int K,
              const float* __restrict__ bias, const float* __restrict__ res)
{
    extern __shared__ char smc[];
    const uint32_t sbase = smem_u32(smc);
    const int tid  = threadIdx.x;
    const int wid  = tid >> 5, lane = tid & 31;
    const int wr   = wid >> 2, wc = wid & 3;     // warp tile: 64(M) x 32(N)
    const int bn   = blockIdx.x * 128;
    const int bm   = blockIdx.y * 128;
    const int NK   = K >> 6;

    float acc[4][4][4];
    #pragma unroll
    for (int i = 0; i < 4; i++)
        #pragma unroll
        for (int j = 0; j < 4; j++)
            #pragma unroll
            for (int k = 0; k < 4; k++) acc[i][j][k] = 0.f;

    mg_load_stage(sbase, 0, tid, Ah, Al, Bh, Bl, bm, bn, K, 0);
    CP_COMMIT();

    for (int it = 0; it < NK; ++it) {
        if (it + 1 < NK) {
            mg_load_stage(sbase, (it + 1) & 1, tid, Ah, Al, Bh, Bl, bm, bn, K, (it + 1) << 6);
            CP_COMMIT();
            CP_WAIT(1);
        } else {
            CP_WAIT(0);
        }
        __syncthreads();

        const uint32_t aBase = sbase + (it & 1) * MG_STAGE;
        const uint32_t bBase = aBase + 32768;

        #pragma unroll
        for (int kk = 0; kk < 4; kk++) {
            uint32_t bh[8], bl[8];
            #pragma unroll
            for (int pair = 0; pair < 2; pair++) {
                int nrow = wc * 32 + pair * 16 + (lane & 7) + ((lane >> 4) << 3);
                int kch  = kk * 2 + ((lane >> 3) & 1);       // 16B chunk index 0..7
                uint32_t byte = nrow * 128 + ((kch ^ (nrow & 7)) << 4);
                ldsm4(bh + pair * 4, bBase + byte);
                ldsm4(bl + pair * 4, bBase + 16384 + byte);
            }
            #pragma unroll
            for (int tm = 0; tm < 4; tm++) {
                int arow = wr * 64 + tm * 16 + (lane & 15);
                int kch  = kk * 2 + (lane >> 4);
                uint32_t byte = arow * 128 + ((kch ^ (arow & 7)) << 4);
                uint32_t ah[4], al[4];
                ldsm4(ah, aBase + byte);
                ldsm4(al, aBase + 16384 + byte);
                #pragma unroll
                for (int tn = 0; tn < 4; tn++) {
                    const uint32_t* bhp = &bh[(tn >> 1) * 4 + (tn & 1) * 2];
                    const uint32_t* blp = &bl[(tn >> 1) * 4 + (tn & 1) * 2];
                    mma_bf16(acc[tm][tn], ah, bhp);
                    mma_bf16(acc[tm][tn], ah, blp);
                    mma_bf16(acc[tm][tn], al, bhp);
                }
            }
        }
        __syncthreads();
    }

    // epilogue
    #pragma unroll
    for (int tm = 0; tm < 4; tm++) {
        #pragma unroll
        for (int tn = 0; tn < 4; tn++) {
            const int row0 = bm + wr * 64 + tm * 16 + (lane >> 2);
            const int col  = bn + wc * 32 + tn * 8 + (lane & 3) * 2;
            float v0 = acc[tm][tn][0], v1 = acc[tm][tn][1];
            float v2 = acc[tm][tn][2], v3 = acc[tm][tn][3];
            if (EPI == 2) {
                const float b0 = bias[col], b1 = bias[col + 1];
                v0 = gelu_f(v0 + b0); v1 = gelu_f(v1 + b1);
                v2 = gelu_f(v2 + b0); v3 = gelu_f(v3 + b1);
                __nv_bfloat162 hp, lp;
                split_bf16(v0, hp.x, lp.x); split_bf16(v1, hp.y, lp.y);
                *(__nv_bfloat162*)(Ch + (size_t)row0 * N + col) = hp;
                *(__nv_bfloat162*)(Cl + (size_t)row0 * N + col) = lp;
                split_bf16(v2, hp.x, lp.x); split_bf16(v3, hp.y, lp.y);
                *(__nv_bfloat162*)(Ch + (size_t)(row0 + 8) * N + col) = hp;
                *(__nv_bfloat162*)(Cl + (size_t)(row0 + 8) * N + col) = lp;
            } else {
                if (EPI == 3) {
                    const float b0 = bias[col], b1 = bias[col + 1];
                    v0 += b0; v1 += b1; v2 += b0; v3 += b1;
                }
                if (EPI == 1 || EPI == 3) {
                    const float2 r0 = *(const float2*)(res + (size_t)row0 * N + col);
                    const float2 r1 = *(const float2*)(res + (size_t)(row0 + 8) * N + col);
                    v0 += r0.x; v1 += r0.y; v2 += r1.x; v3 += r1.y;
                }
                *(float2*)(C + (size_t)row0 * N + col)       = make_float2(v0, v1);
                *(float2*)(C + (size_t)(row0 + 8) * N + col) = make_float2(v2, v3);
            }
        }
    }
}

// ---------------- xPos rotary on fused QKVG buffer -------------------------------
__global__ void xpos_kernel(float* __restrict__ QKVG)
{
    const int idx = blockIdx.x * 256 + threadIdx.x;   // B*S*H*64 threads
    const int j = idx & 63;
    const int h = (idx >> 6) & 7;
    const int s = (idx >> 9) & 2047;
    const int b = idx >> 20;

    const double invf  = exp2(-(double)j * (13.287712379549449 / 64.0));
    const double theta = (double)s * invf;
    const double sv    = (2.0 * j + 0.4 * 128.0) / (1.4 * 128.0);
    const double e     = log2(sv) * ((double)s / 512.0);
    const float scq = (float)exp2(e);
    const float sck = (float)exp2(-e);
    double snd, csd;
    sincos(theta, &snd, &csd);
    const float sn = (float)snd, cs = (float)csd;

    const size_t base = ((size_t)(b * CS + s)) * CNQ + h * CDK + 2 * j;
    const float q0 = QKVG[base], q1 = QKVG[base + 1];
    QKVG[base]     = (q0 * cs - q1 * sn) * scq;
    QKVG[base + 1] = (q1 * cs + q0 * sn) * scq;
    const size_t kb = base + 1024;
    const float k0 = QKVG[kb], k1 = QKVG[kb + 1];
    QKVG[kb]     = (k0 * cs - k1 * sn) * sck;
    QKVG[kb + 1] = (k1 * cs + k0 * sn) * sck;
}

// ---------------- fused retention: Y = (QK^T ∘ decay, causal) V ------------------
__global__ __launch_bounds__(256)
void retention_kernel(const float* __restrict__ QKVG, float* __restrict__ Y)
{
    extern __shared__ float sm[];
    float* Qs   = sm;                 // 64 x 132
    float* Ks   = Qs  + 64 * 132;     // 64 x 132
    float* Vs   = Ks  + 64 * 132;     // 64 x 260
    float* SsT  = Vs  + 64 * 260;     // 64 x 68
    float* rowf = SsT + 64 * 68;      // 64
    float* colf = rowf + 64;          // 64

    const int sb = blockIdx.x, h = blockIdx.y, b = blockIdx.z;
    const int qs = sb * 64;
    const int tid = threadIdx.x;
    const int tx = tid & 31;
    const int ty = tid >> 5;

    const double lg = log(1.0/32.0) + (double)h * ((log(1.0/512.0) - log(1.0/32.0)) / 7.0);
    const float l2g = (float)log2(1.0 - exp(lg));

    const float* Qbase = QKVG + ((size_t)(b * CS + qs)) * CNQ + h * CDK;
    for (int i = tid; i < 64 * 32; i += 256) {
        int r = i >> 5, c4 = (i & 31) << 2;
        *(float4*)(Qs + r * 132 + c4) = *(const float4*)(Qbase + (size_t)r * CNQ + c4);
    }
    if (tid < 64) rowf[tid] = exp2f((float)tid * l2g);

    float acc[8][8];
    #pragma unroll
    for (int i = 0; i < 8; i++)
        #pragma unroll
        for (int j = 0; j < 8; j++) acc[i][j] = 0.f;

    for (int ts = 0; ts <= qs; ts += 64) {
        __syncthreads();
        const float* Kbase = QKVG + ((size_t)(b * CS + ts)) * CNQ + 1024 + h * CDK;
        for (int i = tid; i < 64 * 32; i += 256) {
            int r = i >> 5, c4 = (i & 31) << 2;
            *(float4*)(Ks + r * 132 + c4) = *(const float4*)(Kbase + (size_t)r * CNQ + c4);
        }
        const float* Vbase = QKVG + ((size_t)(b * CS + ts)) * CNQ + 2048 + h * CDV;
        for (int i = tid; i < 64 * 64; i += 256) {
            int r = i >> 6, c4 = (i & 63) << 2;
            *(float4*)(Vs + r * 260 + c4) = *(const float4*)(Vbase + (size_t)r * CNQ + c4);
        }
        if (tid < 64) colf[tid] = exp2f((float)(qs - ts - tid) * l2g);
        __syncthreads();

        float sc[8][2];
        #pragma unroll
        for (int i = 0; i < 8; i++) { sc[i][0] = 0.f; sc[i][1] = 0.f; }

        for (int k4 = 0; k4 < 128; k4 += 4) {
            const float4 kv0 = *(const float4*)(Ks + tx * 132 + k4);
            const float4 kv1 = *(const float4*)(Ks + (tx + 32) * 132 + k4);
            #pragma unroll
            for (int i = 0; i < 8; i++) {
                const float4 qv = *(const float4*)(Qs + (ty * 8 + i) * 132 + k4);
                sc[i][0] += qv.x*kv0.x + qv.y*kv0.y + qv.z*kv0.z + qv.w*kv0.w;
                sc[i][1] += qv.x*kv1.x + qv.y*kv1.y + qv.z*kv1.z + qv.w*kv1.w;
            }
        }
        const bool diag = (ts == qs);
        #pragma unroll
        for (int j = 0; j < 2; j++) {
            const int tp = tx + 32 * j;
            const float cf = colf[tp];
            #pragma unroll
            for (int i = 0; i < 8; i++) {
                const int sp = ty * 8 + i;
                float d = rowf[sp] * cf;
                if (diag && sp < tp) d = 0.f;
                SsT[tp * 68 + sp] = sc[i][j] * d;
            }
        }
        __syncthreads();

        #pragma unroll 4
        for (int t = 0; t < 64; t++) {
            float s8[8];
            *(float4*)(s8)     = *(const float4*)(SsT + t * 68 + ty * 8);
            *(float4*)(s8 + 4) = *(const float4*)(SsT + t * 68 + ty * 8 + 4);
            const float4 va = *(const float4*)(Vs + t * 260 + tx * 4);
            const float4 vb = *(const float4*)(Vs + t * 260 + 128 + tx * 4);
            #pragma unroll
            for (int i = 0; i < 8; i++) {
                acc[i][0] = fmaf(s8[i], va.x, acc[i][0]);
                acc[i][1] = fmaf(s8[i], va.y, acc[i][1]);
                acc[i][2] = fmaf(s8[i], va.z, acc[i][2]);
                acc[i][3] = fmaf(s8[i], va.w, acc[i][3]);
                acc[i][4] = fmaf(s8[i], vb.x, acc[i][4]);
                acc[i][5] = fmaf(s8[i], vb.y, acc[i][5]);
                acc[i][6] = fmaf(s8[i], vb.z, acc[i][6]);
                acc[i][7] = fmaf(s8[i], vb.w, acc[i][7]);
            }
        }
    }

    float* Ybase = Y + ((size_t)(b * CS + qs)) * CVD + h * CDV;
    #pragma unroll
    for (int i = 0; i < 8; i++) {
        const int r = ty * 8 + i;
        *(float4*)(Ybase + (size_t)r * CVD + tx * 4)
            = make_float4(acc[i][0], acc[i][1], acc[i][2], acc[i][3]);
        *(float4*)(Ybase + (size_t)r * CVD + 128 + tx * 4)
            = make_float4(acc[i][4], acc[i][5], acc[i][6], acc[i][7]);
    }
}

// ---------------- groupnorm(DV=256) + SiLU gate -> split bf16 ---------------------
__global__ void gnorm_gate_kernel(const float* __restrict__ Yin, const float* __restrict__ QKVG,
                                  const float* __restrict__ gw, const float* __restrict__ gb,
                                  __nv_bfloat16* __restrict__ oh, __nv_bfloat16* __restrict__ ol)
{
    const int warp = threadIdx.x >> 5, lane = threadIdx.x & 31;
    const int g = blockIdx.x * 8 + warp;     // group = (b*S+s)*H + h
    const int h = g & 7;
    const float4* yb = (const float4*)(Yin + (size_t)g * 256);
    const float4 v0 = yb[lane], v1 = yb[lane + 32];
    float s = v0.x+v0.y+v0.z+v0.w + v1.x+v1.y+v1.z+v1.w;
    float q = v0.x*v0.x+v0.y*v0.y+v0.z*v0.z+v0.w*v0.w
            + v1.x*v1.x+v1.y*v1.y+v1.z*v1.z+v1.w*v1.w;
    s = warpsum(s); q = warpsum(q);
    const float mu  = s * (1.f / 256.f);
    const float var = q * (1.f / 256.f) - mu * mu;
    const float r   = rsqrtf(var + 1e-5f);

    const float4* gB = (const float4*)(QKVG + (size_t)(g >> 3) * CNQ + 4096 + h * 256);
    const float4 g0 = gB[lane], g1 = gB[lane + 32];
    const int c0 = h * 256 + lane * 4, c1 = c0 + 128;
    const float4 w0 = *(const float4*)(gw + c0), w1 = *(const float4*)(gw + c1);
    const float4 b0 = *(const float4*)(gb + c0), b1 = *(const float4*)(gb + c1);

    float o[8];
    o[0] = ((v0.x-mu)*r*w0.x + b0.x) * (g0.x / (1.f + expf(-g0.x)));
    o[1] = ((v0.y-mu)*r*w0.y + b0.y) * (g0.y / (1.f + expf(-g0.y)));
    o[2] = ((v0.z-mu)*r*w0.z + b0.z) * (g0.z / (1.f + expf(-g0.z)));
    o[3] = ((v0.w-mu)*r*w0.w + b0.w) * (g0.w / (1.f + expf(-g0.w)));
    o[4] = ((v1.x-mu)*r*w1.x + b1.x) * (g1.x / (1.f + expf(-g1.x)));
    o[5] = ((v1.y-mu)*r*w1.y + b1.y) * (g1.y / (1.f + expf(-g1.y)));
    o[6] = ((v1.z-mu)*r*w1.z + b1.z) * (g1.z / (1.f + expf(-g1.z)));
    o[7] = ((v1.w-mu)*r*w1.w + b1.w) * (g1.w / (1.f + expf(-g1.w)));

    const size_t base = (size_t)g * 256 + lane * 4;
    __nv_bfloat162 hp, lp;
    split_bf16(o[0], hp.x, lp.x); split_bf16(o[1], hp.y, lp.y);
    *(__nv_bfloat162*)(oh + base) = hp;       *(__nv_bfloat162*)(ol + base) = lp;
    split_bf16(o[2], hp.x, lp.x); split_bf16(o[3], hp.y, lp.y);
    *(__nv_bfloat162*)(oh + base + 2) = hp;   *(__nv_bfloat162*)(ol + base + 2) = lp;
    split_bf16(o[4], hp.x, lp.x); split_bf16(o[5], hp.y, lp.y);
    *(__nv_bfloat162*)(oh + base + 128) = hp; *(__nv_bfloat162*)(ol + base + 128) = lp;
    split_bf16(o[6], hp.x, lp.x); split_bf16(o[7], hp.y, lp.y);
    *(__nv_bfloat162*)(oh + base + 130) = hp; *(__nv_bfloat162*)(ol + base + 130) = lp;
}

// ---------------- launch -----------------------------------------------------------
extern "C" void kernel_launch(void* const* d_in, const int* in_sizes, int n_in,
                              void* d_out, int out_size)
{
    const float* X     = (const float*)d_in[0];
    const float* Wq    = (const float*)d_in[1];
    const float* Wk    = (const float*)d_in[2];
    const float* Wv    = (const float*)d_in[3];
    const float* W_G   = (const float*)d_in[4];
    const float* W_O   = (const float*)d_in[5];
    const float* gn_w  = (const float*)d_in[6];
    const float* gn_b  = (const float*)d_in[7];
    const float* ln1_w = (const float*)d_in[8];
    const float* ln1_b = (const float*)d_in[9];
    const float* ln2_w = (const float*)d_in[10];
    const float* ln2_b = (const float*)d_in[11];
    const float* fw1   = (const float*)d_in[12];
    const float* fb1   = (const float*)d_in[13];
    const float* fw2   = (const float*)d_in[14];
    const float* fb2   = (const float*)d_in[15];

    float *QKVG, *Yb, *X2;
    __nv_bfloat16 *Ah, *Al, *H1h, *H1l, *Wqh, *Wql, *Woh, *Wol, *F1h, *F1l, *F2h, *F2l;
    cudaGetSymbolAddress((void**)&QKVG, g_QKVG);
    cudaGetSymbolAddress((void**)&Yb,   g_Y);
    cudaGetSymbolAddress((void**)&X2,   g_X2);
    cudaGetSymbolAddress((void**)&Ah,   g_Ah);
    cudaGetSymbolAddress((void**)&Al,   g_Al);
    cudaGetSymbolAddress((void**)&H1h,  g_H1h);
    cudaGetSymbolAddress((void**)&H1l,  g_H1l);
    cudaGetSymbolAddress((void**)&Wqh,  g_Wqh);
    cudaGetSymbolAddress((void**)&Wql,  g_Wql);
    cudaGetSymbolAddress((void**)&Woh,  g_Woh);
    cudaGetSymbolAddress((void**)&Wol,  g_Wol);
    cudaGetSymbolAddress((void**)&F1h,  g_F1h);
    cudaGetSymbolAddress((void**)&F1l,  g_F1l);
    cudaGetSymbolAddress((void**)&F2h,  g_F2h);
    cudaGetSymbolAddress((void**)&F2l,  g_F2l);

    const int RET_SMEM = (64*132 + 64*132 + 64*260 + 64*68 + 128) * 4;
    cudaFuncSetAttribute(retention_kernel, cudaFuncAttributeMaxDynamicSharedMemorySize, RET_SMEM);
    const int GSM = 2 * MG_STAGE;   // 131072 B
    cudaFuncSetAttribute(mma_gemm<0>, cudaFuncAttributeMaxDynamicSharedMemorySize, GSM);
    cudaFuncSetAttribute(mma_gemm<1>, cudaFuncAttributeMaxDynamicSharedMemorySize, GSM);
    cudaFuncSetAttribute(mma_gemm<2>, cudaFuncAttributeMaxDynamicSharedMemorySize, GSM);
    cudaFuncSetAttribute(mma_gemm<3>, cudaFuncAttributeMaxDynamicSharedMemorySize, GSM);

    // LN1 -> split A
    ln_split_kernel<<<CBS, 256>>>(X, ln1_w, ln1_b, Ah, Al);

    // pack + split weights (transpose to [N][K])
    pack_split_kernel<<<dim3(32, 32),  256>>>(Wq,  Wqh,           Wql,           CD,   CDK);
    pack_split_kernel<<<dim3(32, 32),  256>>>(Wk,  Wqh + 1024*CD, Wql + 1024*CD, CD,   CDK);
    pack_split_kernel<<<dim3(32, 64),  256>>>(Wv,  Wqh + 2048*CD, Wql + 2048*CD, CD,   CDV);
    pack_split_kernel<<<dim3(32, 64),  256>>>(W_G, Wqh + 4096*CD, Wql + 4096*CD, CD,   CVD);
    pack_split_kernel<<<dim3(64, 32),  256>>>(W_O, Woh, Wol, CVD,  CD);
    pack_split_kernel<<<dim3(32, 128), 256>>>(fw1, F1h, F1l, CD,   CFFN);
    pack_split_kernel<<<dim3(128, 32), 256>>>(fw2, F2h, F2l, CFFN, CD);

    // fused QKVG projection (fp32 out)
    mma_gemm<0><<<dim3(CNQ/128, CBS/128), 256, GSM>>>(Ah, Al, Wqh, Wql,
                                                      QKVG, nullptr, nullptr,
                                                      CNQ, CD, nullptr, nullptr);
    // xPos
    xpos_kernel<<<(CB*CS*CH*64)/256, 256>>>(QKVG);
    // retention
    retention_kernel<<<dim3(CS/64, CH, CB), 256, RET_SMEM>>>(QKVG, Yb);
    // groupnorm + gate -> split A
    gnorm_gate_kernel<<<CBS, 256>>>(Yb, QKVG, gn_w, gn_b, Ah, Al);
    // output projection + residual
    mma_gemm<1><<<dim3(CD/128, CBS/128), 256, GSM>>>(Ah, Al, Woh, Wol,
                                                     X2, nullptr, nullptr,
                                                     CD, CVD, nullptr, X);
    // LN2 -> split A
    ln_split_kernel<<<CBS, 256>>>(X2, ln2_w, ln2_b, Ah, Al);
    // FFN1: bias + gelu -> split H1
    mma_gemm<2><<<dim3(CFFN/128, CBS/128), 256, GSM>>>(Ah, Al, F1h, F1l,
                                                       nullptr, H1h, H1l,
                                                       CFFN, CD, fb1, nullptr);
    // FFN2: bias + residual -> out
    mma_gemm<3><<<dim3(CD/128, CBS/128), 256, GSM>>>(H1h, H1l, F2h, F2l,
                                                     (float*)d_out, nullptr, nullptr,
                                                     CD, CFFN, fb2, X2);
}

// round 10
// speedup vs baseline: 2.5554x; 1.3359x over previous
#include <cuda_runtime.h>
#include <cuda_bf16.h>
#include <math.h>
#include <stdint.h>

#define CB   2
#define CS   2048
#define CD   1024
#define CH   8
#define CDK  128
#define CVD  2048
#define CDV  256
#define CFFN 4096
#define CBS  (CB*CS)     // 4096 rows
#define CNQ  6144        // fused Q|K|V|G width

// ---------------- scratch (device globals; no allocation allowed) -------------
__device__ float g_QKVG[(size_t)CBS*CNQ];
__device__ float g_Y   [(size_t)CBS*CVD];
__device__ float g_X2  [(size_t)CBS*CD];
__device__ __nv_bfloat16 g_Ah [(size_t)CBS*2048], g_Al [(size_t)CBS*2048];
__device__ __nv_bfloat16 g_H1h[(size_t)CBS*CFFN], g_H1l[(size_t)CBS*CFFN];
__device__ __nv_bfloat16 g_Wqh[(size_t)CNQ*CD],  g_Wql[(size_t)CNQ*CD];
__device__ __nv_bfloat16 g_Woh[(size_t)CD*CVD],  g_Wol[(size_t)CD*CVD];
__device__ __nv_bfloat16 g_F1h[(size_t)CFFN*CD], g_F1l[(size_t)CFFN*CD];
__device__ __nv_bfloat16 g_F2h[(size_t)CD*CFFN], g_F2l[(size_t)CD*CFFN];
// retention operands, [b][h][s][dk/dv]
__device__ __nv_bfloat16 g_Qh[(size_t)CBS*CD],  g_Ql[(size_t)CBS*CD];
__device__ __nv_bfloat16 g_Kh[(size_t)CBS*CD],  g_Kl[(size_t)CBS*CD];
__device__ __nv_bfloat16 g_Vh[(size_t)CBS*CVD], g_Vl[(size_t)CBS*CVD];

// ================= PTX helpers (base sm_103 — no 'a' features) =================
__device__ __forceinline__ uint32_t smem_u32(const void* p) {
    uint32_t a;
    asm("{ .reg .u64 t; cvta.to.shared.u64 t, %1; cvt.u32.u64 %0, t; }" : "=r"(a) : "l"(p));
    return a;
}
#define CP_ASYNC16(dst, src) \
    asm volatile("cp.async.cg.shared.global [%0], [%1], 16;" :: "r"(dst), "l"(src))
#define CP_COMMIT() asm volatile("cp.async.commit_group;" ::: "memory")
#define CP_WAIT(n)  asm volatile("cp.async.wait_group %0;" :: "n"(n) : "memory")

__device__ __forceinline__ void ldsm4(uint32_t* r, uint32_t addr) {
    asm volatile("ldmatrix.sync.aligned.m8n8.x4.shared.b16 {%0,%1,%2,%3}, [%4];"
        : "=r"(r[0]), "=r"(r[1]), "=r"(r[2]), "=r"(r[3]) : "r"(addr));
}
__device__ __forceinline__ void ldsm4t(uint32_t* r, uint32_t addr) {
    asm volatile("ldmatrix.sync.aligned.m8n8.x4.trans.shared.b16 {%0,%1,%2,%3}, [%4];"
        : "=r"(r[0]), "=r"(r[1]), "=r"(r[2]), "=r"(r[3]) : "r"(addr));
}
__device__ __forceinline__ void mma_bf16(float* d, const uint32_t* a, const uint32_t* b) {
    asm volatile("mma.sync.aligned.m16n8k16.row.col.f32.bf16.bf16.f32 "
        "{%0,%1,%2,%3}, {%4,%5,%6,%7}, {%8,%9}, {%0,%1,%2,%3};"
        : "+f"(d[0]), "+f"(d[1]), "+f"(d[2]), "+f"(d[3])
        : "r"(a[0]), "r"(a[1]), "r"(a[2]), "r"(a[3]), "r"(b[0]), "r"(b[1]));
}

// ---------------- misc helpers -------------------------------------------------
__device__ __forceinline__ float warpsum(float v) {
    #pragma unroll
    for (int o = 16; o; o >>= 1) v += __shfl_xor_sync(0xffffffffu, v, o);
    return v;
}
__device__ __forceinline__ float gelu_f(float x) {
    return 0.5f * x * (1.0f + erff(x * 0.70710678118654752f));
}
__device__ __forceinline__ void split_bf16(float x, __nv_bfloat16& h, __nv_bfloat16& l) {
    h = __float2bfloat16(x);
    l = __float2bfloat16(x - __bfloat162float(h));
}
__device__ __forceinline__ uint32_t pack_split_hi(float a, float b) {
    __nv_bfloat162 p;
    p.x = __float2bfloat16(a);
    p.y = __float2bfloat16(b);
    return *(uint32_t*)&p;
}
__device__ __forceinline__ uint32_t pack_split_lo(float a, float b) {
    __nv_bfloat16 ha = __float2bfloat16(a), hb = __float2bfloat16(b);
    __nv_bfloat162 p;
    p.x = __float2bfloat16(a - __bfloat162float(ha));
    p.y = __float2bfloat16(b - __bfloat162float(hb));
    return *(uint32_t*)&p;
}

// ---------------- layernorm over D=1024 -> split bf16 --------------------------
__global__ void ln_split_kernel(const float* __restrict__ x, const float* __restrict__ w,
                                const float* __restrict__ bb,
                                __nv_bfloat16* __restrict__ yh, __nv_bfloat16* __restrict__ yl)
{
    __shared__ float s_sum[8], s_sq[8];
    __shared__ float s_mu, s_rstd;
    const int row = blockIdx.x;
    const int tid = threadIdx.x;
    const float4 v = ((const float4*)(x + (size_t)row * CD))[tid];
    float s = v.x + v.y + v.z + v.w;
    float q = v.x*v.x + v.y*v.y + v.z*v.z + v.w*v.w;
    s = warpsum(s); q = warpsum(q);
    if ((tid & 31) == 0) { s_sum[tid >> 5] = s; s_sq[tid >> 5] = q; }
    __syncthreads();
    if (tid == 0) {
        float ts = 0.f, tq = 0.f;
        #pragma unroll
        for (int i = 0; i < 8; i++) { ts += s_sum[i]; tq += s_sq[i]; }
        float mu  = ts * (1.f / CD);
        float var = tq * (1.f / CD) - mu * mu;
        s_mu = mu; s_rstd = rsqrtf(var + 1e-5f);
    }
    __syncthreads();
    const float mu = s_mu, r = s_rstd;
    const float4 wv = ((const float4*)w)[tid];
    const float4 bv = ((const float4*)bb)[tid];
    float o0 = (v.x - mu) * r * wv.x + bv.x;
    float o1 = (v.y - mu) * r * wv.y + bv.y;
    float o2 = (v.z - mu) * r * wv.z + bv.z;
    float o3 = (v.w - mu) * r * wv.w + bv.w;
    __nv_bfloat162 hA, hB, lA, lB;
    split_bf16(o0, hA.x, lA.x); split_bf16(o1, hA.y, lA.y);
    split_bf16(o2, hB.x, lB.x); split_bf16(o3, hB.y, lB.y);
    const size_t base = (size_t)row * CD + tid * 4;
    *(__nv_bfloat162*)(yh + base)     = hA;
    *(__nv_bfloat162*)(yh + base + 2) = hB;
    *(__nv_bfloat162*)(yl + base)     = lA;
    *(__nv_bfloat162*)(yl + base + 2) = lB;
}

// ---------------- weight pack: transpose + bf16 split ---------------------------
__global__ void pack_split_kernel(const float* __restrict__ src,
                                  __nv_bfloat16* __restrict__ dh, __nv_bfloat16* __restrict__ dl,
                                  int Dd, int Kk)
{
    __shared__ float t[32][33];
    const int lx = threadIdx.x & 31, ly = threadIdx.x >> 5;
    const int d0 = blockIdx.x * 32;
    const int r0 = blockIdx.y * 32;
    const int h  = r0 / Kk;
    const int k0 = r0 - h * Kk;
    const float* s = src + (size_t)h * Dd * Kk;
    #pragma unroll
    for (int i = ly; i < 32; i += 8)
        t[i][lx] = s[(size_t)(d0 + i) * Kk + k0 + lx];
    __syncthreads();
    #pragma unroll
    for (int i = ly; i < 32; i += 8) {
        float x = t[lx][i];
        __nv_bfloat16 hh, ll;
        split_bf16(x, hh, ll);
        dh[(size_t)(r0 + i) * Dd + d0 + lx] = hh;
        dl[(size_t)(r0 + i) * Dd + d0 + lx] = ll;
    }
}

// ---------------- mma.sync split-bf16 GEMM (128x128 tile, Ktile=64, 2 stages) ---
#define MG_STAGE 65536

__device__ __forceinline__ void mg_load_stage(
    uint32_t sbase, int st, int tid,
    const __nv_bfloat16* __restrict__ Ah, const __nv_bfloat16* __restrict__ Al,
    const __nv_bfloat16* __restrict__ Bh, const __nv_bfloat16* __restrict__ Bl,
    int bm, int bn, int K, int kt)
{
    const uint32_t stb = sbase + st * MG_STAGE;
    #pragma unroll
    for (int i = 0; i < 16; i++) {
        int idx  = tid + i * 256;
        int half = idx >> 11;
        int m    = (idx >> 10) & 1;
        int r    = (idx >> 3) & 127;
        int c    = idx & 7;
        const __nv_bfloat16* g = half ? (m ? Bl : Bh) : (m ? Al : Ah);
        const __nv_bfloat16* src = g + (size_t)((half ? bn : bm) + r) * K + kt + c * 8;
        uint32_t dst = stb + (half << 15) + (m << 14) + r * 128 + ((c ^ (r & 7)) << 4);
        CP_ASYNC16(dst, src);
    }
}

// EPI: 0 fp32 store; 1 +res; 2 +bias->gelu->split bf16; 3 +bias+res
template<int EPI>
__global__ __launch_bounds__(256, 1)
void mma_gemm(const __nv_bfloat16* __restrict__ Ah, const __nv_bfloat16* __restrict__ Al,
              const __nv_bfloat16* __restrict__ Bh, const __nv_bfloat16* __restrict__ Bl,
              float* __restrict__ C,
              __nv_bfloat16* __restrict__ Ch, __nv_bfloat16* __restrict__ Cl,
              int N, int K,
              const float* __restrict__ bias, const float* __restrict__ res)
{
    extern __shared__ char smc[];
    const uint32_t sbase = smem_u32(smc);
    const int tid  = threadIdx.x;
    const int wid  = tid >> 5, lane = tid & 31;
    const int wr   = wid >> 2, wc = wid & 3;
    const int bn   = blockIdx.x * 128;
    const int bm   = blockIdx.y * 128;
    const int NK   = K >> 6;

    float acc[4][4][4];
    #pragma unroll
    for (int i = 0; i < 4; i++)
        #pragma unroll
        for (int j = 0; j < 4; j++)
            #pragma unroll
            for (int k = 0; k < 4; k++) acc[i][j][k] = 0.f;

    mg_load_stage(sbase, 0, tid, Ah, Al, Bh, Bl, bm, bn, K, 0);
    CP_COMMIT();

    for (int it = 0; it < NK; ++it) {
        if (it + 1 < NK) {
            mg_load_stage(sbase, (it + 1) & 1, tid, Ah, Al, Bh, Bl, bm, bn, K, (it + 1) << 6);
            CP_COMMIT();
            CP_WAIT(1);
        } else {
            CP_WAIT(0);
        }
        __syncthreads();

        const uint32_t aBase = sbase + (it & 1) * MG_STAGE;
        const uint32_t bBase = aBase + 32768;

        #pragma unroll
        for (int kk = 0; kk < 4; kk++) {
            uint32_t bh[8], bl[8];
            #pragma unroll
            for (int pair = 0; pair < 2; pair++) {
                int nrow = wc * 32 + pair * 16 + (lane & 7) + ((lane >> 4) << 3);
                int kch  = kk * 2 + ((lane >> 3) & 1);
                uint32_t byte = nrow * 128 + ((kch ^ (nrow & 7)) << 4);
                ldsm4(bh + pair * 4, bBase + byte);
                ldsm4(bl + pair * 4, bBase + 16384 + byte);
            }
            #pragma unroll
            for (int tm = 0; tm < 4; tm++) {
                int arow = wr * 64 + tm * 16 + (lane & 15);
                int kch  = kk * 2 + (lane >> 4);
                uint32_t byte = arow * 128 + ((kch ^ (arow & 7)) << 4);
                uint32_t ah[4], al[4];
                ldsm4(ah, aBase + byte);
                ldsm4(al, aBase + 16384 + byte);
                #pragma unroll
                for (int tn = 0; tn < 4; tn++) {
                    const uint32_t* bhp = &bh[(tn >> 1) * 4 + (tn & 1) * 2];
                    const uint32_t* blp = &bl[(tn >> 1) * 4 + (tn & 1) * 2];
                    mma_bf16(acc[tm][tn], ah, bhp);
                    mma_bf16(acc[tm][tn], ah, blp);
                    mma_bf16(acc[tm][tn], al, bhp);
                }
            }
        }
        __syncthreads();
    }

    #pragma unroll
    for (int tm = 0; tm < 4; tm++) {
        #pragma unroll
        for (int tn = 0; tn < 4; tn++) {
            const int row0 = bm + wr * 64 + tm * 16 + (lane >> 2);
            const int col  = bn + wc * 32 + tn * 8 + (lane & 3) * 2;
            float v0 = acc[tm][tn][0], v1 = acc[tm][tn][1];
            float v2 = acc[tm][tn][2], v3 = acc[tm][tn][3];
            if (EPI == 2) {
                const float b0 = bias[col], b1 = bias[col + 1];
                v0 = gelu_f(v0 + b0); v1 = gelu_f(v1 + b1);
                v2 = gelu_f(v2 + b0); v3 = gelu_f(v3 + b1);
                __nv_bfloat162 hp, lp;
                split_bf16(v0, hp.x, lp.x); split_bf16(v1, hp.y, lp.y);
                *(__nv_bfloat162*)(Ch + (size_t)row0 * N + col) = hp;
                *(__nv_bfloat162*)(Cl + (size_t)row0 * N + col) = lp;
                split_bf16(v2, hp.x, lp.x); split_bf16(v3, hp.y, lp.y);
                *(__nv_bfloat162*)(Ch + (size_t)(row0 + 8) * N + col) = hp;
                *(__nv_bfloat162*)(Cl + (size_t)(row0 + 8) * N + col) = lp;
            } else {
                if (EPI == 3) {
                    const float b0 = bias[col], b1 = bias[col + 1];
                    v0 += b0; v1 += b1; v2 += b0; v3 += b1;
                }
                if (EPI == 1 || EPI == 3) {
                    const float2 r0 = *(const float2*)(res + (size_t)row0 * N + col);
                    const float2 r1 = *(const float2*)(res + (size_t)(row0 + 8) * N + col);
                    v0 += r0.x; v1 += r0.y; v2 += r1.x; v3 += r1.y;
                }
                *(float2*)(C + (size_t)row0 * N + col)       = make_float2(v0, v1);
                *(float2*)(C + (size_t)(row0 + 8) * N + col) = make_float2(v2, v3);
            }
        }
    }
}

// ---------------- xPos rotary -> split bf16 [b][h][s][128] ------------------------
__global__ void xpos_split_kernel(const float* __restrict__ QKVG,
                                  __nv_bfloat16* __restrict__ Qh, __nv_bfloat16* __restrict__ Ql,
                                  __nv_bfloat16* __restrict__ Kh, __nv_bfloat16* __restrict__ Kl)
{
    const int idx = blockIdx.x * 256 + threadIdx.x;   // B*S*H*64 threads
    const int j = idx & 63;
    const int h = (idx >> 6) & 7;
    const int s = (idx >> 9) & 2047;
    const int b = idx >> 20;

    const double invf  = exp2(-(double)j * (13.287712379549449 / 64.0));
    const double theta = (double)s * invf;
    const double sv    = (2.0 * j + 0.4 * 128.0) / (1.4 * 128.0);
    const double e     = log2(sv) * ((double)s / 512.0);
    const float scq = (float)exp2(e);
    const float sck = (float)exp2(-e);
    double snd, csd;
    sincos(theta, &snd, &csd);
    const float sn = (float)snd, cs = (float)csd;

    const size_t src = ((size_t)(b * CS + s)) * CNQ + h * CDK + 2 * j;
    const float q0 = QKVG[src], q1 = QKVG[src + 1];
    const float k0 = QKVG[src + 1024], k1 = QKVG[src + 1025];
    const float qo0 = (q0 * cs - q1 * sn) * scq;
    const float qo1 = (q1 * cs + q0 * sn) * scq;
    const float ko0 = (k0 * cs - k1 * sn) * sck;
    const float ko1 = (k1 * cs + k0 * sn) * sck;

    const size_t dst = (((size_t)(b * CH + h)) * CS + s) * CDK + 2 * j;
    __nv_bfloat162 hp, lp;
    split_bf16(qo0, hp.x, lp.x); split_bf16(qo1, hp.y, lp.y);
    *(__nv_bfloat162*)(Qh + dst) = hp;  *(__nv_bfloat162*)(Ql + dst) = lp;
    split_bf16(ko0, hp.x, lp.x); split_bf16(ko1, hp.y, lp.y);
    *(__nv_bfloat162*)(Kh + dst) = hp;  *(__nv_bfloat162*)(Kl + dst) = lp;
}

// ---------------- V split -> [b][h][s][256] ----------------------------------------
__global__ void v_split_kernel(const float* __restrict__ QKVG,
                               __nv_bfloat16* __restrict__ Vh, __nv_bfloat16* __restrict__ Vl)
{
    const int idx = blockIdx.x * 256 + threadIdx.x;   // B*S*H*128 threads
    const int j = idx & 127;
    const int h = (idx >> 7) & 7;
    const int s = (idx >> 10) & 2047;
    const int b = idx >> 21;
    const size_t src = ((size_t)(b * CS + s)) * CNQ + 2048 + h * CDV + 2 * j;
    const float v0 = QKVG[src], v1 = QKVG[src + 1];
    const size_t dst = (((size_t)(b * CH + h)) * CS + s) * CDV + 2 * j;
    __nv_bfloat162 hp, lp;
    split_bf16(v0, hp.x, lp.x); split_bf16(v1, hp.y, lp.y);
    *(__nv_bfloat162*)(Vh + dst) = hp;  *(__nv_bfloat162*)(Vl + dst) = lp;
}

// ---------------- mma retention: Y = (QK^T ∘ decay, causal) V ----------------------
// stage: Kh 16K | Kl 16K | Vh 32K | Vl 32K = 96K; 2 stages + decay tables
#define RT_STAGE 98304

__device__ __forceinline__ void ret_load_stage(
    uint32_t sbase, int st, int tid,
    const __nv_bfloat16* __restrict__ Khb, const __nv_bfloat16* __restrict__ Klb,
    const __nv_bfloat16* __restrict__ Vhb, const __nv_bfloat16* __restrict__ Vlb,
    int ts)
{
    const uint32_t stb = sbase + st * RT_STAGE;
    #pragma unroll
    for (int i = 0; i < 8; i++) {         // K hi|lo: 2 x 64 rows x 256B
        int idx = tid + i * 256;
        int m = idx >> 10;
        int r = (idx >> 4) & 63;
        int c = idx & 15;
        const __nv_bfloat16* src = (m ? Klb : Khb) + (size_t)(ts + r) * CDK + c * 8;
        uint32_t dst = stb + (m << 14) + r * 256 + ((c ^ (r & 7)) << 4);
        CP_ASYNC16(dst, src);
    }
    #pragma unroll
    for (int i = 0; i < 16; i++) {        // V hi|lo: 2 x 64 rows x 512B
        int idx = tid + i * 256;
        int m = idx >> 11;
        int r = (idx >> 5) & 63;
        int c = idx & 31;
        const __nv_bfloat16* src = (m ? Vlb : Vhb) + (size_t)(ts + r) * CDV + c * 8;
        uint32_t dst = stb + 32768 + (m << 15) + r * 512 + ((c ^ (r & 7)) << 4);
        CP_ASYNC16(dst, src);
    }
}

__global__ __launch_bounds__(256, 1)
void ret_mma_kernel(const __nv_bfloat16* __restrict__ Qh, const __nv_bfloat16* __restrict__ Ql,
                    const __nv_bfloat16* __restrict__ Kh, const __nv_bfloat16* __restrict__ Kl,
                    const __nv_bfloat16* __restrict__ Vh, const __nv_bfloat16* __restrict__ Vl,
                    float* __restrict__ Y)
{
    extern __shared__ char smc[];
    const uint32_t sbase = smem_u32(smc);
    float* rowf = (float*)(smc + 2 * RT_STAGE);
    float* ctf  = rowf + 64;

    const int qb = gridDim.x - 1 - blockIdx.x;     // heavy blocks first
    const int h  = blockIdx.y, b = blockIdx.z;
    const int qs = qb * 64;
    const int tid = threadIdx.x;
    const int wid = tid >> 5, lane = tid & 31;
    const int wr  = wid >> 1, wc = wid & 1;        // 4(M) x 2(N), warp = 16 x 128
    const int NT  = qb + 1;

    const double lg = log(1.0/32.0) + (double)h * ((log(1.0/512.0) - log(1.0/32.0)) / 7.0);
    const float l2g = (float)log2(1.0 - exp(lg));

    if (tid < 64) {
        rowf[tid] = exp2f(l2g * (float)tid);
        ctf[tid]  = exp2f(-l2g * (float)tid);
    }

    const size_t hb = ((size_t)(b * CH + h)) * CS;
    const __nv_bfloat16* Qhb = Qh + (hb + qs) * CDK;
    const __nv_bfloat16* Qlb = Ql + (hb + qs) * CDK;
    const __nv_bfloat16* Khb = Kh + hb * CDK;
    const __nv_bfloat16* Klb = Kl + hb * CDK;
    const __nv_bfloat16* Vhb = Vh + hb * CDV;
    const __nv_bfloat16* Vlb = Vl + hb * CDV;

    // Q fragments direct from gmem (A-fragment layout), rows = wr*16 + lane>>2 (+8)
    const int r0 = wr * 16 + (lane >> 2);
    uint32_t qfh[8][4], qfl[8][4];
    #pragma unroll
    for (int kf = 0; kf < 8; kf++) {
        const int k0 = kf * 16 + (lane & 3) * 2;
        qfh[kf][0] = *(const uint32_t*)(Qhb + (size_t)r0 * CDK + k0);
        qfh[kf][1] = *(const uint32_t*)(Qhb + (size_t)(r0 + 8) * CDK + k0);
        qfh[kf][2] = *(const uint32_t*)(Qhb + (size_t)r0 * CDK + k0 + 8);
        qfh[kf][3] = *(const uint32_t*)(Qhb + (size_t)(r0 + 8) * CDK + k0 + 8);
        qfl[kf][0] = *(const uint32_t*)(Qlb + (size_t)r0 * CDK + k0);
        qfl[kf][1] = *(const uint32_t*)(Qlb + (size_t)(r0 + 8) * CDK + k0);
        qfl[kf][2] = *(const uint32_t*)(Qlb + (size_t)r0 * CDK + k0 + 8);
        qfl[kf][3] = *(const uint32_t*)(Qlb + (size_t)(r0 + 8) * CDK + k0 + 8);
    }

    float yacc[16][4];
    #pragma unroll
    for (int i = 0; i < 16; i++)
        #pragma unroll
        for (int j = 0; j < 4; j++) yacc[i][j] = 0.f;

    ret_load_stage(sbase, 0, tid, Khb, Klb, Vhb, Vlb, 0);
    CP_COMMIT();

    for (int it = 0; it < NT; ++it) {
        if (it + 1 < NT) {
            ret_load_stage(sbase, (it + 1) & 1, tid, Khb, Klb, Vhb, Vlb, (it + 1) * 64);
            CP_COMMIT();
            CP_WAIT(1);
        } else {
            CP_WAIT(0);
        }
        __syncthreads();

        const uint32_t Kb0 = sbase + (it & 1) * RT_STAGE;
        const uint32_t Vb0 = Kb0 + 32768;

        // ---- S = Q K^T (split, 3 mma) over k=128, n = 64 t-cols ----
        float sacc[8][4];
        #pragma unroll
        for (int i = 0; i < 8; i++)
            #pragma unroll
            for (int j = 0; j < 4; j++) sacc[i][j] = 0.f;

        #pragma unroll
        for (int kf = 0; kf < 8; kf++) {
            uint32_t bh[16], bl[16];
            #pragma unroll
            for (int g = 0; g < 4; g++) {
                int nrow = g * 16 + (lane & 7) + ((lane >> 4) << 3);
                int kch  = kf * 2 + ((lane >> 3) & 1);
                uint32_t byte = nrow * 256 + ((kch ^ (nrow & 7)) << 4);
                ldsm4(bh + g * 4, Kb0 + byte);
                ldsm4(bl + g * 4, Kb0 + 16384 + byte);
            }
            #pragma unroll
            for (int nt = 0; nt < 8; nt++) {
                const uint32_t* ph = &bh[(nt >> 1) * 4 + (nt & 1) * 2];
                const uint32_t* pl = &bl[(nt >> 1) * 4 + (nt & 1) * 2];
                mma_bf16(sacc[nt], qfh[kf], ph);
                mma_bf16(sacc[nt], qfh[kf], pl);
                mma_bf16(sacc[nt], qfl[kf], ph);
            }
        }

        // ---- decay + mask + split S to A-fragments ----
        const float cb = exp2f(l2g * (float)(qs - it * 64));
        const float rA = rowf[r0 & 63] * cb;
        const float rB = rowf[(r0 + 8) & 63] * cb;
        const bool diag = (it == NT - 1);
        const int cA = (lane & 3) * 2;

        uint32_t sfh[4][4], sfl[4][4];
        #pragma unroll
        for (int p = 0; p < 4; p++) {
            #pragma unroll
            for (int half = 0; half < 2; half++) {
                const int nt = 2 * p + half;
                const int c0 = nt * 8 + cA;
                const float ct0 = ctf[c0], ct1 = ctf[c0 + 1];
                float s0 = sacc[nt][0] * rA * ct0;
                float s1 = sacc[nt][1] * rA * ct1;
                float s2 = sacc[nt][2] * rB * ct0;
                float s3 = sacc[nt][3] * rB * ct1;
                if (diag) {
                    if (r0 < c0)     s0 = 0.f;
                    if (r0 < c0 + 1) s1 = 0.f;
                    if (r0 + 8 < c0)     s2 = 0.f;
                    if (r0 + 8 < c0 + 1) s3 = 0.f;
                }
                sfh[p][half * 2 + 0] = pack_split_hi(s0, s1);
                sfh[p][half * 2 + 1] = pack_split_hi(s2, s3);
                sfl[p][half * 2 + 0] = pack_split_lo(s0, s1);
                sfl[p][half * 2 + 1] = pack_split_lo(s2, s3);
            }
        }
        // reorder: A-frag regs are {a0,a1,a2,a3} = {(r,k0),(r+8,k0),(r,k8),(r+8,k8)}
        // our fill order above already gives [half*2+0]=(r,...),(r+8,...) per half => matches.

        // ---- Y += S V (split, 3 mma), V fragments via ldmatrix.trans ----
        #pragma unroll
        for (int p = 0; p < 4; p++) {
            #pragma unroll
            for (int ng = 0; ng < 8; ng++) {
                int row = p * 16 + (lane & 7) + ((lane >> 3) & 1) * 8;
                int cn  = wc * 16 + ng * 2 + (lane >> 4);
                uint32_t byte = row * 512 + ((cn ^ (row & 7)) << 4);
                uint32_t vh[4], vl[4];
                ldsm4t(vh, Vb0 + byte);
                ldsm4t(vl, Vb0 + 32768 + byte);
                mma_bf16(yacc[ng * 2],     sfh[p], vh);
                mma_bf16(yacc[ng * 2],     sfh[p], vl);
                mma_bf16(yacc[ng * 2],     sfl[p], vh);
                mma_bf16(yacc[ng * 2 + 1], sfh[p], vh + 2);
                mma_bf16(yacc[ng * 2 + 1], sfh[p], vl + 2);
                mma_bf16(yacc[ng * 2 + 1], sfl[p], vh + 2);
            }
        }
        __syncthreads();
    }

    // ---- epilogue: Y layout [b][s][h*256 + v] ----
    const int srow = qs + r0;
    #pragma unroll
    for (int nt = 0; nt < 16; nt++) {
        const int col = wc * 128 + nt * 8 + (lane & 3) * 2;
        float* y0 = Y + ((size_t)(b * CS + srow)) * CVD + h * CDV + col;
        *(float2*)y0              = make_float2(yacc[nt][0], yacc[nt][1]);
        *(float2*)(y0 + 8 * CVD)  = make_float2(yacc[nt][2], yacc[nt][3]);
    }
}

// ---------------- groupnorm(DV=256) + SiLU gate -> split bf16 ---------------------
__global__ void gnorm_gate_kernel(const float* __restrict__ Yin, const float* __restrict__ QKVG,
                                  const float* __restrict__ gw, const float* __restrict__ gb,
                                  __nv_bfloat16* __restrict__ oh, __nv_bfloat16* __restrict__ ol)
{
    const int warp = threadIdx.x >> 5, lane = threadIdx.x & 31;
    const int g = blockIdx.x * 8 + warp;     // group = (b*S+s)*H + h
    const int h = g & 7;
    const float4* yb = (const float4*)(Yin + (size_t)g * 256);
    const float4 v0 = yb[lane], v1 = yb[lane + 32];
    float s = v0.x+v0.y+v0.z+v0.w + v1.x+v1.y+v1.z+v1.w;
    float q = v0.x*v0.x+v0.y*v0.y+v0.z*v0.z+v0.w*v0.w
            + v1.x*v1.x+v1.y*v1.y+v1.z*v1.z+v1.w*v1.w;
    s = warpsum(s); q = warpsum(q);
    const float mu  = s * (1.f / 256.f);
    const float var = q * (1.f / 256.f) - mu * mu;
    const float r   = rsqrtf(var + 1e-5f);

    const float4* gB = (const float4*)(QKVG + (size_t)(g >> 3) * CNQ + 4096 + h * 256);
    const float4 g0 = gB[lane], g1 = gB[lane + 32];
    const int c0 = h * 256 + lane * 4, c1 = c0 + 128;
    const float4 w0 = *(const float4*)(gw + c0), w1 = *(const float4*)(gw + c1);
    const float4 b0 = *(const float4*)(gb + c0), b1 = *(const float4*)(gb + c1);

    float o[8];
    o[0] = ((v0.x-mu)*r*w0.x + b0.x) * (g0.x / (1.f + expf(-g0.x)));
    o[1] = ((v0.y-mu)*r*w0.y + b0.y) * (g0.y / (1.f + expf(-g0.y)));
    o[2] = ((v0.z-mu)*r*w0.z + b0.z) * (g0.z / (1.f + expf(-g0.z)));
    o[3] = ((v0.w-mu)*r*w0.w + b0.w) * (g0.w / (1.f + expf(-g0.w)));
    o[4] = ((v1.x-mu)*r*w1.x + b1.x) * (g1.x / (1.f + expf(-g1.x)));
    o[5] = ((v1.y-mu)*r*w1.y + b1.y) * (g1.y / (1.f + expf(-g1.y)));
    o[6] = ((v1.z-mu)*r*w1.z + b1.z) * (g1.z / (1.f + expf(-g1.z)));
    o[7] = ((v1.w-mu)*r*w1.w + b1.w) * (g1.w / (1.f + expf(-g1.w)));

    const size_t base = (size_t)g * 256 + lane * 4;
    __nv_bfloat162 hp, lp;
    split_bf16(o[0], hp.x, lp.x); split_bf16(o[1], hp.y, lp.y);
    *(__nv_bfloat162*)(oh + base) = hp;       *(__nv_bfloat162*)(ol + base) = lp;
    split_bf16(o[2], hp.x, lp.x); split_bf16(o[3], hp.y, lp.y);
    *(__nv_bfloat162*)(oh + base + 2) = hp;   *(__nv_bfloat162*)(ol + base + 2) = lp;
    split_bf16(o[4], hp.x, lp.x); split_bf16(o[5], hp.y, lp.y);
    *(__nv_bfloat162*)(oh + base + 128) = hp; *(__nv_bfloat162*)(ol + base + 128) = lp;
    split_bf16(o[6], hp.x, lp.x); split_bf16(o[7], hp.y, lp.y);
    *(__nv_bfloat162*)(oh + base + 130) = hp; *(__nv_bfloat162*)(ol + base + 130) = lp;
}

// ---------------- launch -----------------------------------------------------------
extern "C" void kernel_launch(void* const* d_in, const int* in_sizes, int n_in,
                              void* d_out, int out_size)
{
    const float* X     = (const float*)d_in[0];
    const float* Wq    = (const float*)d_in[1];
    const float* Wk    = (const float*)d_in[2];
    const float* Wv    = (const float*)d_in[3];
    const float* W_G   = (const float*)d_in[4];
    const float* W_O   = (const float*)d_in[5];
    const float* gn_w  = (const float*)d_in[6];
    const float* gn_b  = (const float*)d_in[7];
    const float* ln1_w = (const float*)d_in[8];
    const float* ln1_b = (const float*)d_in[9];
    const float* ln2_w = (const float*)d_in[10];
    const float* ln2_b = (const float*)d_in[11];
    const float* fw1   = (const float*)d_in[12];
    const float* fb1   = (const float*)d_in[13];
    const float* fw2   = (const float*)d_in[14];
    const float* fb2   = (const float*)d_in[15];

    float *QKVG, *Yb, *X2;
    __nv_bfloat16 *Ah, *Al, *H1h, *H1l, *Wqh, *Wql, *Woh, *Wol, *F1h, *F1l, *F2h, *F2l;
    __nv_bfloat16 *Qh, *Ql, *Kh, *Kl, *Vh, *Vl;
    cudaGetSymbolAddress((void**)&QKVG, g_QKVG);
    cudaGetSymbolAddress((void**)&Yb,   g_Y);
    cudaGetSymbolAddress((void**)&X2,   g_X2);
    cudaGetSymbolAddress((void**)&Ah,   g_Ah);
    cudaGetSymbolAddress((void**)&Al,   g_Al);
    cudaGetSymbolAddress((void**)&H1h,  g_H1h);
    cudaGetSymbolAddress((void**)&H1l,  g_H1l);
    cudaGetSymbolAddress((void**)&Wqh,  g_Wqh);
    cudaGetSymbolAddress((void**)&Wql,  g_Wql);
    cudaGetSymbolAddress((void**)&Woh,  g_Woh);
    cudaGetSymbolAddress((void**)&Wol,  g_Wol);
    cudaGetSymbolAddress((void**)&F1h,  g_F1h);
    cudaGetSymbolAddress((void**)&F1l,  g_F1l);
    cudaGetSymbolAddress((void**)&F2h,  g_F2h);
    cudaGetSymbolAddress((void**)&F2l,  g_F2l);
    cudaGetSymbolAddress((void**)&Qh,   g_Qh);
    cudaGetSymbolAddress((void**)&Ql,   g_Ql);
    cudaGetSymbolAddress((void**)&Kh,   g_Kh);
    cudaGetSymbolAddress((void**)&Kl,   g_Kl);
    cudaGetSymbolAddress((void**)&Vh,   g_Vh);
    cudaGetSymbolAddress((void**)&Vl,   g_Vl);

    const int GSM = 2 * MG_STAGE;               // 131072 B
    cudaFuncSetAttribute(mma_gemm<0>, cudaFuncAttributeMaxDynamicSharedMemorySize, GSM);
    cudaFuncSetAttribute(mma_gemm<1>, cudaFuncAttributeMaxDynamicSharedMemorySize, GSM);
    cudaFuncSetAttribute(mma_gemm<2>, cudaFuncAttributeMaxDynamicSharedMemorySize, GSM);
    cudaFuncSetAttribute(mma_gemm<3>, cudaFuncAttributeMaxDynamicSharedMemorySize, GSM);
    const int RSM = 2 * RT_STAGE + 512;         // 197120 B
    cudaFuncSetAttribute(ret_mma_kernel, cudaFuncAttributeMaxDynamicSharedMemorySize, RSM);

    // LN1 -> split A
    ln_split_kernel<<<CBS, 256>>>(X, ln1_w, ln1_b, Ah, Al);

    // pack + split weights (transpose to [N][K])
    pack_split_kernel<<<dim3(32, 32),  256>>>(Wq,  Wqh,           Wql,           CD,   CDK);
    pack_split_kernel<<<dim3(32, 32),  256>>>(Wk,  Wqh + 1024*CD, Wql + 1024*CD, CD,   CDK);
    pack_split_kernel<<<dim3(32, 64),  256>>>(Wv,  Wqh + 2048*CD, Wql + 2048*CD, CD,   CDV);
    pack_split_kernel<<<dim3(32, 64),  256>>>(W_G, Wqh + 4096*CD, Wql + 4096*CD, CD,   CVD);
    pack_split_kernel<<<dim3(64, 32),  256>>>(W_O, Woh, Wol, CVD,  CD);
    pack_split_kernel<<<dim3(32, 128), 256>>>(fw1, F1h, F1l, CD,   CFFN);
    pack_split_kernel<<<dim3(128, 32), 256>>>(fw2, F2h, F2l, CFFN, CD);

    // fused QKVG projection (fp32 out)
    mma_gemm<0><<<dim3(CNQ/128, CBS/128), 256, GSM>>>(Ah, Al, Wqh, Wql,
                                                      QKVG, nullptr, nullptr,
                                                      CNQ, CD, nullptr, nullptr);
    // xPos + split Q/K; split V
    xpos_split_kernel<<<(CB*CS*CH*64)/256, 256>>>(QKVG, Qh, Ql, Kh, Kl);
    v_split_kernel<<<(CB*CS*CH*128)/256, 256>>>(QKVG, Vh, Vl);
    // retention (tensor cores)
    ret_mma_kernel<<<dim3(CS/64, CH, CB), 256, RSM>>>(Qh, Ql, Kh, Kl, Vh, Vl, Yb);
    // groupnorm + gate -> split A
    gnorm_gate_kernel<<<CBS, 256>>>(Yb, QKVG, gn_w, gn_b, Ah, Al);
    // output projection + residual
    mma_gemm<1><<<dim3(CD/128, CBS/128), 256, GSM>>>(Ah, Al, Woh, Wol,
                                                     X2, nullptr, nullptr,
                                                     CD, CVD, nullptr, X);
    // LN2 -> split A
    ln_split_kernel<<<CBS, 256>>>(X2, ln2_w, ln2_b, Ah, Al);
    // FFN1: bias + gelu -> split H1
    mma_gemm<2><<<dim3(CFFN/128, CBS/128), 256, GSM>>>(Ah, Al, F1h, F1l,
                                                       nullptr, H1h, H1l,
                                                       CFFN, CD, fb1, nullptr);
    // FFN2: bias + residual -> out
    mma_gemm<3><<<dim3(CD/128, CBS/128), 256, GSM>>>(H1h, H1l, F2h, F2l,
                                                     (float*)d_out, nullptr, nullptr,
                                                     CD, CFFN, fb2, X2);
}